// round 6
// baseline (speedup 1.0000x reference)
#include <cuda_runtime.h>
#include <cuda_bf16.h>
#include <math.h>
#include <stdint.h>

#define N_NODES 2048
#define D_DIM   128
#define E_DIM   8
#define GITERS  8
#define K_BIG   (N_NODES * E_DIM)   /* 16384 */

/* ---------------- scratch layout (floats) ---------------- */
#define OFF_H0    0L
#define OFF_H1    262144L
#define OFF_MSG   524288L
#define OFF_GI    786432L                 /* [2048][384] */
#define OFF_GH    1572864L
#define OFF_HA    2359296L
#define SCRATCH_FLOATS 2621440L

__device__ float g_scratch[SCRATCH_FLOATS];

__device__ __align__(16) __nv_bfloat16 g_edgeK_hi[(long)N_NODES * K_BIG];  /* [t][e*2048+s] */
__device__ __align__(16) __nv_bfloat16 g_edgeK_lo[(long)N_NODES * K_BIG];
__device__ __align__(16) __nv_bfloat16 g_Pt_hi[(long)D_DIM * K_BIG];       /* [d][e*2048+s] */
__device__ __align__(16) __nv_bfloat16 g_Pt_lo[(long)D_DIM * K_BIG];
__device__ __align__(16) __nv_bfloat16 g_part_hi[16L * N_NODES * D_DIM];   /* [p][t][d] */
__device__ __align__(16) __nv_bfloat16 g_part_lo[16L * N_NODES * D_DIM];

/* ================= helpers ================= */
__device__ __forceinline__ uint32_t smem_u32(const void* p) {
    uint32_t a;
    asm("{ .reg .u64 t; cvta.to.shared.u64 t, %1; cvt.u32.u64 %0, t; }" : "=r"(a) : "l"(p));
    return a;
}
__device__ __forceinline__ void ldsm_x4(uint32_t addr, uint32_t& r0, uint32_t& r1,
                                        uint32_t& r2, uint32_t& r3) {
    asm volatile("ldmatrix.sync.aligned.m8n8.x4.shared.b16 {%0,%1,%2,%3}, [%4];"
                 : "=r"(r0), "=r"(r1), "=r"(r2), "=r"(r3) : "r"(addr));
}
__device__ __forceinline__ void ldsm_x2(uint32_t addr, uint32_t& r0, uint32_t& r1) {
    asm volatile("ldmatrix.sync.aligned.m8n8.x2.shared.b16 {%0,%1}, [%2];"
                 : "=r"(r0), "=r"(r1) : "r"(addr));
}
__device__ __forceinline__ void mma_bf16(float* c, const uint32_t* a, const uint32_t* b) {
    asm volatile("mma.sync.aligned.m16n8k16.row.col.f32.bf16.bf16.f32 "
                 "{%0,%1,%2,%3}, {%4,%5,%6,%7}, {%8,%9}, {%0,%1,%2,%3};"
                 : "+f"(c[0]), "+f"(c[1]), "+f"(c[2]), "+f"(c[3])
                 : "r"(a[0]), "r"(a[1]), "r"(a[2]), "r"(a[3]), "r"(b[0]), "r"(b[1]));
}
__device__ __forceinline__ void cp_async16(uint32_t saddr, const void* gaddr) {
    asm volatile("cp.async.cg.shared.global [%0], [%1], 16;" :: "r"(saddr), "l"(gaddr) : "memory");
}
#define CP_COMMIT() asm volatile("cp.async.commit_group;" ::: "memory")
#define CP_WAIT2()  asm volatile("cp.async.wait_group 2;" ::: "memory")

__device__ __forceinline__ void split4(float4 v, __nv_bfloat16* hb, __nv_bfloat16* lb) {
    float f[4] = { v.x, v.y, v.z, v.w };
#pragma unroll
    for (int j = 0; j < 4; j++) {
        __nv_bfloat16 h = __float2bfloat16(f[j]);
        hb[j] = h;
        lb[j] = __float2bfloat16(f[j] - __bfloat162float(h));
    }
}
__device__ __forceinline__ void store_split2(__nv_bfloat16* hp, __nv_bfloat16* lp,
                                             long off, float x, float y) {
    __nv_bfloat16 hx = __float2bfloat16(x), hy = __float2bfloat16(y);
    __nv_bfloat16 lx = __float2bfloat16(x - __bfloat162float(hx));
    __nv_bfloat16 ly = __float2bfloat16(y - __bfloat162float(hy));
    __nv_bfloat162 hv; hv.x = hx; hv.y = hy;
    __nv_bfloat162 lv; lv.x = lx; lv.y = ly;
    *(__nv_bfloat162*)(hp + off) = hv;
    *(__nv_bfloat162*)(lp + off) = lv;
}

/* fill split smem tile [128 rows][128 k] (256B rows, xor-swizzled) */
__device__ __forceinline__ void load_split_rowk(char* smc, uint32_t hioff, uint32_t looff,
        const float* __restrict__ g, int ldg, int tid)
{
#pragma unroll
    for (int i = 0; i < 16; i++) {
        int lin = i * 256 + tid;
        int row = lin >> 5, c4 = lin & 31;
        float4 v = *(const float4*)&g[(long)row * ldg + c4 * 4];
        __align__(8) __nv_bfloat16 hb[4], lb[4];
        split4(v, hb, lb);
        uint32_t off = row * 256 + (((c4 >> 1) ^ (row & 7)) << 4) + ((c4 & 1) << 3);
        *(uint2*)(smc + hioff + off) = *(const uint2*)hb;
        *(uint2*)(smc + looff + off) = *(const uint2*)lb;
    }
}

/* fill split smem tile Bs[n][k] from B[k][n0+n] fp32 */
__device__ __forceinline__ void load_split_coln(char* smc, uint32_t hioff, uint32_t looff,
        const float* __restrict__ g, int ldg, int tid)
{
    const int n = tid & 127;
#pragma unroll
    for (int i = 0; i < 16; i++) {
        int kg = i * 2 + (tid >> 7);
        float4 v;
        v.x = g[(long)(kg * 4 + 0) * ldg + n];
        v.y = g[(long)(kg * 4 + 1) * ldg + n];
        v.z = g[(long)(kg * 4 + 2) * ldg + n];
        v.w = g[(long)(kg * 4 + 3) * ldg + n];
        __align__(8) __nv_bfloat16 hb[4], lb[4];
        split4(v, hb, lb);
        uint32_t off = n * 256 + (((kg >> 1) ^ (n & 7)) << 4) + ((kg & 1) << 3);
        *(uint2*)(smc + hioff + off) = *(const uint2*)hb;
        *(uint2*)(smc + looff + off) = *(const uint2*)lb;
    }
}

/* K=128 one-shot mma core */
__device__ __forceinline__ void mma_k128(uint32_t sb, uint32_t ah, uint32_t al,
        uint32_t bh, uint32_t bl, float acc[4][4][4], int warpM, int warpN, int lane)
{
#pragma unroll
    for (int ks = 0; ks < 8; ks++) {
        uint32_t Bh[4][2], Bl[4][2];
        const int cb = ks * 2 + ((lane >> 3) & 1);
#pragma unroll
        for (int nt = 0; nt < 4; nt++) {
            int row = warpN * 32 + nt * 8 + (lane & 7);
            uint32_t off = row * 256 + ((cb ^ (row & 7)) << 4);
            ldsm_x2(sb + bh + off, Bh[nt][0], Bh[nt][1]);
            ldsm_x2(sb + bl + off, Bl[nt][0], Bl[nt][1]);
        }
        const int ca = ks * 2 + (lane >> 4);
#pragma unroll
        for (int mt = 0; mt < 4; mt++) {
            int row = warpM * 64 + mt * 16 + (lane & 15);
            uint32_t off = row * 256 + ((ca ^ (row & 7)) << 4);
            uint32_t Ah[4], Al[4];
            ldsm_x4(sb + ah + off, Ah[0], Ah[1], Ah[2], Ah[3]);
            ldsm_x4(sb + al + off, Al[0], Al[1], Al[2], Al[3]);
#pragma unroll
            for (int nt = 0; nt < 4; nt++) {
                mma_bf16(acc[mt][nt], Ah, Bh[nt]);
                mma_bf16(acc[mt][nt], Al, Bh[nt]);
                mma_bf16(acc[mt][nt], Ah, Bl[nt]);
            }
        }
    }
}

#define T32K 32768u

/* ---------------- generic C = A@B (+bias) via HMMA, K=128 ---------------- */
__global__ void __launch_bounds__(256) lin_mma(const float* __restrict__ A,
        const float* __restrict__ B, const float* __restrict__ bias,
        float* __restrict__ C, int N)
{
    extern __shared__ char smc[];
    const uint32_t sb = smem_u32(smc);
    const int tid = threadIdx.x, wid = tid >> 5, lane = tid & 31;
    const int warpM = wid >> 2, warpN = wid & 3;
    const int m0 = blockIdx.x * 128, n0 = blockIdx.y * 128;

    load_split_rowk(smc, 0, T32K, A + (long)m0 * 128, 128, tid);
    load_split_coln(smc, 2 * T32K, 3 * T32K, B + n0, N, tid);
    __syncthreads();

    float acc[4][4][4] = {};
    mma_k128(sb, 0, T32K, 2 * T32K, 3 * T32K, acc, warpM, warpN, lane);

    const int gr = lane >> 2, idx = lane & 3;
#pragma unroll
    for (int mt = 0; mt < 4; mt++) {
        int r0 = m0 + warpM * 64 + mt * 16 + gr;
#pragma unroll
        for (int nt = 0; nt < 4; nt++) {
            int col = n0 + warpN * 32 + nt * 8 + 2 * idx;
            float b0 = bias ? bias[col] : 0.f;
            float b1 = bias ? bias[col + 1] : 0.f;
            *(float2*)&C[(long)r0 * N + col] =
                make_float2(acc[mt][nt][0] + b0, acc[mt][nt][1] + b1);
            *(float2*)&C[(long)(r0 + 8) * N + col] =
                make_float2(acc[mt][nt][2] + b0, acc[mt][nt][3] + b1);
        }
    }
}

/* ---------------- per-edge transform, transposed-split output ---------------- */
__global__ void __launch_bounds__(256) pe_mma(const float* __restrict__ h,
                                              const float* __restrict__ Wmsg)
{
    extern __shared__ char smc[];
    const uint32_t sb = smem_u32(smc);
    const int tid = threadIdx.x, wid = tid >> 5, lane = tid & 31;
    const int warpM = wid >> 2, warpN = wid & 3;
    const int s0 = blockIdx.x * 128, e = blockIdx.y;

    load_split_rowk(smc, 0, T32K, h + (long)s0 * 128, 128, tid);
    load_split_coln(smc, 2 * T32K, 3 * T32K, Wmsg + (long)e * 16384, 128, tid);
    __syncthreads();

    float acc[4][4][4] = {};
    mma_k128(sb, 0, T32K, 2 * T32K, 3 * T32K, acc, warpM, warpN, lane);

    __syncthreads();
    float* tb = (float*)smc;                      /* [128 d][132] */
    const int gr = lane >> 2, idx = lane & 3;
#pragma unroll
    for (int mt = 0; mt < 4; mt++) {
        int sr = warpM * 64 + mt * 16 + gr;
#pragma unroll
        for (int nt = 0; nt < 4; nt++) {
            int d = warpN * 32 + nt * 8 + 2 * idx;
            tb[d * 132 + sr]           = acc[mt][nt][0];
            tb[(d + 1) * 132 + sr]     = acc[mt][nt][1];
            tb[d * 132 + sr + 8]       = acc[mt][nt][2];
            tb[(d + 1) * 132 + sr + 8] = acc[mt][nt][3];
        }
    }
    __syncthreads();
#pragma unroll
    for (int i = 0; i < 16; i++) {
        int lin = i * 256 + tid;
        int d = lin >> 5, c4 = lin & 31;
        int s = c4 * 4;
        float4 v = *(const float4*)&tb[d * 132 + s];
        __align__(8) __nv_bfloat16 hb[4], lb[4];
        split4(v, hb, lb);
        long o = (long)d * K_BIG + (long)e * 2048 + s0 + s;
        *(uint2*)&g_Pt_hi[o] = *(const uint2*)hb;
        *(uint2*)&g_Pt_lo[o] = *(const uint2*)lb;
    }
}

/* ---------------- readout NT ---------------- */
__global__ void __launch_bounds__(256) nt_mma(const float* __restrict__ hA,
        const float* __restrict__ h, float* __restrict__ C)
{
    extern __shared__ char smc[];
    const uint32_t sb = smem_u32(smc);
    const int tid = threadIdx.x, wid = tid >> 5, lane = tid & 31;
    const int warpM = wid >> 2, warpN = wid & 3;
    const int i0 = blockIdx.x * 128, j0 = blockIdx.y * 128;

    load_split_rowk(smc, 0, T32K, hA + (long)i0 * 128, 128, tid);
    load_split_rowk(smc, 2 * T32K, 3 * T32K, h + (long)j0 * 128, 128, tid);
    __syncthreads();

    float acc[4][4][4] = {};
    mma_k128(sb, 0, T32K, 2 * T32K, 3 * T32K, acc, warpM, warpN, lane);

    const int gr = lane >> 2, idx = lane & 3;
#pragma unroll
    for (int mt = 0; mt < 4; mt++) {
        int r0 = i0 + warpM * 64 + mt * 16 + gr;
#pragma unroll
        for (int nt = 0; nt < 4; nt++) {
            int col = j0 + warpN * 32 + nt * 8 + 2 * idx;
            *(float2*)&C[(long)r0 * N_NODES + col] = make_float2(acc[mt][nt][0], acc[mt][nt][1]);
            *(float2*)&C[(long)(r0 + 8) * N_NODES + col] = make_float2(acc[mt][nt][2], acc[mt][nt][3]);
        }
    }
}

/* =============== one-time edge transpose+split (coalesced writes) =============== */
__global__ void edge_split_kernel(const float* __restrict__ edge)
{
    __shared__ float sm[64][133];
    const int s0 = blockIdx.x * 64, t0 = blockIdx.y * 16;
    const int tid = threadIdx.x;
#pragma unroll
    for (int it = 0; it < 8; it++) {
        int lin = it * 256 + tid;
        int s_l = lin >> 5, f4 = lin & 31;
        float4 v = *(const float4*)&edge[(long)(s0 + s_l) * K_BIG + t0 * 8 + f4 * 4];
        sm[s_l][f4 * 4 + 0] = v.x; sm[s_l][f4 * 4 + 1] = v.y;
        sm[s_l][f4 * 4 + 2] = v.z; sm[s_l][f4 * 4 + 3] = v.w;
    }
    __syncthreads();
#pragma unroll
    for (int it = 0; it < 4; it++) {
        int lin = it * 256 + tid;
        int sc  = lin & 7;
        int e   = (lin >> 3) & 7;
        int t_l = lin >> 6;
        __align__(16) __nv_bfloat16 hb[8], lb[8];
#pragma unroll
        for (int j = 0; j < 8; j++) {
            float f = sm[sc * 8 + j][t_l * 8 + e];
            __nv_bfloat16 h = __float2bfloat16(f);
            hb[j] = h;
            lb[j] = __float2bfloat16(f - __bfloat162float(h));
        }
        long o = (long)(t0 + t_l) * K_BIG + (long)e * 2048 + s0 + sc * 8;
        *(uint4*)&g_edgeK_hi[o] = *(const uint4*)hb;
        *(uint4*)&g_edgeK_lo[o] = *(const uint4*)lb;
    }
}

/* =============== big message GEMM (pipelined HMMA) =============== */
#define MTILE_B 8192u
#define MSTAGE_B 32768u

__global__ void __launch_bounds__(256, 2) msg_mma_kernel()
{
    extern __shared__ char smc[];
    const uint32_t sb = smem_u32(smc);
    const int tid = threadIdx.x;
    const int wid = tid >> 5, lane = tid & 31;
    const int warpM = wid >> 2, warpN = wid & 3;
    const int t0 = blockIdx.x * 128;
    const int e = blockIdx.y, sh = blockIdx.z;
    const long koff = (long)e * 2048 + sh * 1024;

    const __nv_bfloat16* __restrict__ bAh = g_edgeK_hi + (long)t0 * K_BIG + koff;
    const __nv_bfloat16* __restrict__ bAl = g_edgeK_lo + (long)t0 * K_BIG + koff;
    const __nv_bfloat16* __restrict__ bBh = g_Pt_hi + koff;
    const __nv_bfloat16* __restrict__ bBl = g_Pt_lo + koff;

    float acc[4][4][4] = {};

    auto issue = [&](int chunk, int st) {
        const int kofs = chunk * 32;
        const __nv_bfloat16* srcs[4] = { bAh + kofs, bAl + kofs, bBh + kofs, bBl + kofs };
        const uint32_t stage = sb + st * MSTAGE_B;
#pragma unroll
        for (int j = 0; j < 4; j++) {
#pragma unroll
            for (int it = 0; it < 2; it++) {
                int seg = it * 256 + tid;
                int row = seg >> 2, c = seg & 3;
                uint32_t saddr = stage + j * MTILE_B + row * 64 +
                                 ((c ^ ((row >> 1) & 3)) << 4);
                cp_async16(saddr, srcs[j] + (long)row * K_BIG + c * 8);
            }
        }
    };

    issue(0, 0); CP_COMMIT();
    issue(1, 1); CP_COMMIT();
    issue(2, 2); CP_COMMIT();

    for (int chunk = 0; chunk < 32; chunk++) {
        CP_WAIT2();
        __syncthreads();
        const uint32_t stage = sb + (chunk % 3) * MSTAGE_B;

        /* hoisted B fragments for both k16 halves via ldmatrix.x4 */
        uint32_t Bh[2][4][2], Bl[2][4][2];
        {
            const int cb = lane >> 3;   /* kblock 0..3 */
#pragma unroll
            for (int nt = 0; nt < 4; nt++) {
                int row = warpN * 32 + nt * 8 + (lane & 7);
                uint32_t off = row * 64 + ((cb ^ ((row >> 1) & 3)) << 4);
                ldsm_x4(stage + 2 * MTILE_B + off,
                        Bh[0][nt][0], Bh[0][nt][1], Bh[1][nt][0], Bh[1][nt][1]);
                ldsm_x4(stage + 3 * MTILE_B + off,
                        Bl[0][nt][0], Bl[0][nt][1], Bl[1][nt][0], Bl[1][nt][1]);
            }
        }
#pragma unroll
        for (int ks = 0; ks < 2; ks++) {
            const int ca = ks * 2 + (lane >> 4);
#pragma unroll
            for (int mt = 0; mt < 4; mt++) {
                int row = warpM * 64 + mt * 16 + (lane & 15);
                uint32_t off = row * 64 + ((ca ^ ((row >> 1) & 3)) << 4);
                uint32_t Ah[4], Al[4];
                ldsm_x4(stage + off, Ah[0], Ah[1], Ah[2], Ah[3]);
                ldsm_x4(stage + MTILE_B + off, Al[0], Al[1], Al[2], Al[3]);
#pragma unroll
                for (int nt = 0; nt < 4; nt++) {
                    mma_bf16(acc[mt][nt], Ah, Bh[ks][nt]);
                    mma_bf16(acc[mt][nt], Al, Bh[ks][nt]);
                    mma_bf16(acc[mt][nt], Ah, Bl[ks][nt]);
                }
            }
        }
        __syncthreads();
        if (chunk + 3 < 32) issue(chunk + 3, chunk % 3);
        CP_COMMIT();
    }

    const int gr = lane >> 2, idx = lane & 3;
    const long pbase = (long)(e + 8 * sh) * N_NODES * D_DIM;
#pragma unroll
    for (int mt = 0; mt < 4; mt++) {
        int r0 = t0 + warpM * 64 + mt * 16 + gr;
#pragma unroll
        for (int nt = 0; nt < 4; nt++) {
            int col = warpN * 32 + nt * 8 + 2 * idx;
            store_split2(g_part_hi, g_part_lo, pbase + (long)r0 * D_DIM + col,
                         acc[mt][nt][0], acc[mt][nt][1]);
            store_split2(g_part_hi, g_part_lo, pbase + (long)(r0 + 8) * D_DIM + col,
                         acc[mt][nt][2], acc[mt][nt][3]);
        }
    }
}

/* ---------------- reduce 16 bf16-split partials + bias (8-wide) ---------------- */
__global__ void reduce_bias(const float* __restrict__ bias)
{
    long idx = ((long)blockIdx.x * 256 + threadIdx.x) * 8;   /* < 262144 */
    int d0 = (int)(idx & 127);
    float s[8];
#pragma unroll
    for (int j = 0; j < 8; j++) s[j] = bias[d0 + j];
#pragma unroll
    for (int p = 0; p < 16; p++) {
        uint4 h4 = *(const uint4*)&g_part_hi[(long)p * 262144 + idx];
        uint4 l4 = *(const uint4*)&g_part_lo[(long)p * 262144 + idx];
        const __nv_bfloat162* hp = (const __nv_bfloat162*)&h4;
        const __nv_bfloat162* lp = (const __nv_bfloat162*)&l4;
#pragma unroll
        for (int q = 0; q < 4; q++) {
            s[2 * q + 0] += __bfloat162float(hp[q].x) + __bfloat162float(lp[q].x);
            s[2 * q + 1] += __bfloat162float(hp[q].y) + __bfloat162float(lp[q].y);
        }
    }
    *(float4*)&g_scratch[OFF_MSG + idx]     = make_float4(s[0], s[1], s[2], s[3]);
    *(float4*)&g_scratch[OFF_MSG + idx + 4] = make_float4(s[4], s[5], s[6], s[7]);
}

/* ---------------- GRU elementwise update ---------------- */
__global__ void gru_kernel(int cur)
{
    int idx = blockIdx.x * 256 + threadIdx.x;
    int i = idx >> 7, d = idx & 127;
    const float* __restrict__ gi = g_scratch + OFF_GI;
    const float* __restrict__ gh = g_scratch + OFF_GH;
    const float* __restrict__ h  = g_scratch + (cur ? OFF_H1 : OFF_H0);
    float* __restrict__ ho = g_scratch + (cur ? OFF_H0 : OFF_H1);

    long base = (long)i * 384 + d;
    float ir = gi[base], iz = gi[base + 128], inn = gi[base + 256];
    float hr = gh[base], hz = gh[base + 128], hn  = gh[base + 256];
    float hv = h[idx];
    float r = 1.f / (1.f + expf(-(ir + hr)));
    float z = 1.f / (1.f + expf(-(iz + hz)));
    float n = tanhf(inn + r * hn);
    ho[idx] = (1.f - z) * n + z * hv;
}

/* ---------------- launcher (two-stream fork/join graph) ---------------- */
extern "C" void kernel_launch(void* const* d_in, const int* in_sizes, int n_in,
                              void* d_out, int out_size)
{
    const float* node = (const float*)d_in[0];
    const float* edge = (const float*)d_in[1];
    const float* Wmsg = (const float*)d_in[2];
    const float* bmsg = (const float*)d_in[3];
    const float* Wi   = (const float*)d_in[4];
    const float* Wh   = (const float*)d_in[5];
    const float* bgru = (const float*)d_in[6];
    const float* Aro  = (const float*)d_in[7];
    float* out = (float*)d_out;

    float* scratch = nullptr;
    cudaGetSymbolAddress((void**)&scratch, g_scratch);
    float* H0  = scratch + OFF_H0;
    float* H1  = scratch + OFF_H1;
    float* MSG = scratch + OFF_MSG;
    float* GI  = scratch + OFF_GI;
    float* GH  = scratch + OFF_GH;
    float* HA  = scratch + OFF_HA;

    /* host-side handles, created once outside capture (first call is the
     * uncaptured correctness run); identical device work every call */
    static cudaStream_t s1 = nullptr;
    static cudaEvent_t evH = nullptr, evGH = nullptr, evE = nullptr;
    if (!s1) {
        cudaStreamCreateWithFlags(&s1, cudaStreamNonBlocking);
        cudaEventCreateWithFlags(&evH, cudaEventDisableTiming);
        cudaEventCreateWithFlags(&evGH, cudaEventDisableTiming);
        cudaEventCreateWithFlags(&evE, cudaEventDisableTiming);
    }

    cudaFuncSetAttribute(msg_mma_kernel, cudaFuncAttributeMaxDynamicSharedMemorySize, 3 * MSTAGE_B);
    cudaFuncSetAttribute(lin_mma, cudaFuncAttributeMaxDynamicSharedMemorySize, 131072);
    cudaFuncSetAttribute(pe_mma, cudaFuncAttributeMaxDynamicSharedMemorySize, 131072);
    cudaFuncSetAttribute(nt_mma, cudaFuncAttributeMaxDynamicSharedMemorySize, 131072);

    cudaMemcpyAsync(H0, node, (size_t)N_NODES * D_DIM * sizeof(float),
                    cudaMemcpyDeviceToDevice);
    cudaEventRecord(evH, 0);                     /* h ready; also fork point */

    /* edge transpose+split on side stream, overlapped with pe(0) */
    cudaStreamWaitEvent(s1, evH, 0);
    edge_split_kernel<<<dim3(32, 128), 256, 0, s1>>>(edge);
    cudaEventRecord(evE, s1);

    int cur = 0;
    for (int it = 0; it < GITERS; it++) {
        float* Hc = cur ? H1 : H0;

        pe_mma<<<dim3(16, 8), 256, 131072>>>(Hc, Wmsg);

        /* GH = h @ Wh on side stream, hidden under pe/msg/reduce/GI */
        if (it > 0) cudaStreamWaitEvent(s1, evH, 0);
        lin_mma<<<dim3(16, 3), 256, 131072, s1>>>(Hc, Wh, nullptr, GH, 384);
        cudaEventRecord(evGH, s1);

        if (it == 0) cudaStreamWaitEvent(0, evE, 0);
        msg_mma_kernel<<<dim3(16, 8, 2), 256, 3 * MSTAGE_B>>>();
        reduce_bias<<<128, 256>>>(bmsg);
        lin_mma<<<dim3(16, 3), 256, 131072>>>(MSG, Wi, bgru, GI, 384);

        cudaStreamWaitEvent(0, evGH, 0);
        gru_kernel<<<1024, 256>>>(cur);
        cudaEventRecord(evH, 0);
        cur ^= 1;
    }
    float* Hf = cur ? H1 : H0;
    lin_mma<<<dim3(16, 1), 256, 131072>>>(Hf, Aro, nullptr, HA, 128);
    nt_mma<<<dim3(16, 16), 256, 131072>>>(HA, Hf, out);
}

// round 7
// speedup vs baseline: 1.0087x; 1.0087x over previous
#include <cuda_runtime.h>
#include <cuda_bf16.h>
#include <math.h>
#include <stdint.h>

#define N_NODES 2048
#define D_DIM   128
#define E_DIM   8
#define GITERS  8
#define K_BIG   (N_NODES * E_DIM)   /* 16384 */

/* ---------------- scratch layout (floats) ---------------- */
#define OFF_H0    0L
#define OFF_H1    262144L
#define OFF_MSG   524288L
#define OFF_GI    786432L                 /* [2048][384] */
#define OFF_GH    1572864L
#define OFF_HA    2359296L
#define SCRATCH_FLOATS 2621440L

__device__ float g_scratch[SCRATCH_FLOATS];

__device__ __align__(16) __nv_bfloat16 g_edgeK_hi[(long)N_NODES * K_BIG];  /* [t][e*2048+s] */
__device__ __align__(16) __nv_bfloat16 g_edgeK_lo[(long)N_NODES * K_BIG];
__device__ __align__(16) __nv_bfloat16 g_Pt_hi[(long)D_DIM * K_BIG];       /* [d][e*2048+s] */
__device__ __align__(16) __nv_bfloat16 g_Pt_lo[(long)D_DIM * K_BIG];
__device__ __align__(16) __nv_bfloat16 g_part_hi[16L * N_NODES * D_DIM];   /* [p][t][d] */
__device__ __align__(16) __nv_bfloat16 g_part_lo[16L * N_NODES * D_DIM];

/* ================= helpers ================= */
__device__ __forceinline__ uint32_t smem_u32(const void* p) {
    uint32_t a;
    asm("{ .reg .u64 t; cvta.to.shared.u64 t, %1; cvt.u32.u64 %0, t; }" : "=r"(a) : "l"(p));
    return a;
}
__device__ __forceinline__ void ldsm_x4(uint32_t addr, uint32_t& r0, uint32_t& r1,
                                        uint32_t& r2, uint32_t& r3) {
    asm volatile("ldmatrix.sync.aligned.m8n8.x4.shared.b16 {%0,%1,%2,%3}, [%4];"
                 : "=r"(r0), "=r"(r1), "=r"(r2), "=r"(r3) : "r"(addr));
}
__device__ __forceinline__ void ldsm_x2(uint32_t addr, uint32_t& r0, uint32_t& r1) {
    asm volatile("ldmatrix.sync.aligned.m8n8.x2.shared.b16 {%0,%1}, [%2];"
                 : "=r"(r0), "=r"(r1) : "r"(addr));
}
__device__ __forceinline__ void mma_bf16(float* c, const uint32_t* a, const uint32_t* b) {
    asm volatile("mma.sync.aligned.m16n8k16.row.col.f32.bf16.bf16.f32 "
                 "{%0,%1,%2,%3}, {%4,%5,%6,%7}, {%8,%9}, {%0,%1,%2,%3};"
                 : "+f"(c[0]), "+f"(c[1]), "+f"(c[2]), "+f"(c[3])
                 : "r"(a[0]), "r"(a[1]), "r"(a[2]), "r"(a[3]), "r"(b[0]), "r"(b[1]));
}
__device__ __forceinline__ void cp_async16(uint32_t saddr, const void* gaddr) {
    asm volatile("cp.async.cg.shared.global [%0], [%1], 16;" :: "r"(saddr), "l"(gaddr) : "memory");
}
#define CP_COMMIT() asm volatile("cp.async.commit_group;" ::: "memory")
#define CP_WAIT2()  asm volatile("cp.async.wait_group 2;" ::: "memory")

__device__ __forceinline__ void split4(float4 v, __nv_bfloat16* hb, __nv_bfloat16* lb) {
    float f[4] = { v.x, v.y, v.z, v.w };
#pragma unroll
    for (int j = 0; j < 4; j++) {
        __nv_bfloat16 h = __float2bfloat16(f[j]);
        hb[j] = h;
        lb[j] = __float2bfloat16(f[j] - __bfloat162float(h));
    }
}
__device__ __forceinline__ void store_split2(__nv_bfloat16* hp, __nv_bfloat16* lp,
                                             long off, float x, float y) {
    __nv_bfloat16 hx = __float2bfloat16(x), hy = __float2bfloat16(y);
    __nv_bfloat16 lx = __float2bfloat16(x - __bfloat162float(hx));
    __nv_bfloat16 ly = __float2bfloat16(y - __bfloat162float(hy));
    __nv_bfloat162 hv; hv.x = hx; hv.y = hy;
    __nv_bfloat162 lv; lv.x = lx; lv.y = ly;
    *(__nv_bfloat162*)(hp + off) = hv;
    *(__nv_bfloat162*)(lp + off) = lv;
}

/* fill split smem tile [128 rows][128 k] (256B rows, xor-swizzled) */
__device__ __forceinline__ void load_split_rowk(char* smc, uint32_t hioff, uint32_t looff,
        const float* __restrict__ g, int ldg, int tid)
{
#pragma unroll
    for (int i = 0; i < 16; i++) {
        int lin = i * 256 + tid;
        int row = lin >> 5, c4 = lin & 31;
        float4 v = *(const float4*)&g[(long)row * ldg + c4 * 4];
        __align__(8) __nv_bfloat16 hb[4], lb[4];
        split4(v, hb, lb);
        uint32_t off = row * 256 + (((c4 >> 1) ^ (row & 7)) << 4) + ((c4 & 1) << 3);
        *(uint2*)(smc + hioff + off) = *(const uint2*)hb;
        *(uint2*)(smc + looff + off) = *(const uint2*)lb;
    }
}

/* fill split smem tile Bs[n][k] from B[k][n0+n] fp32 */
__device__ __forceinline__ void load_split_coln(char* smc, uint32_t hioff, uint32_t looff,
        const float* __restrict__ g, int ldg, int tid)
{
    const int n = tid & 127;
#pragma unroll
    for (int i = 0; i < 16; i++) {
        int kg = i * 2 + (tid >> 7);
        float4 v;
        v.x = g[(long)(kg * 4 + 0) * ldg + n];
        v.y = g[(long)(kg * 4 + 1) * ldg + n];
        v.z = g[(long)(kg * 4 + 2) * ldg + n];
        v.w = g[(long)(kg * 4 + 3) * ldg + n];
        __align__(8) __nv_bfloat16 hb[4], lb[4];
        split4(v, hb, lb);
        uint32_t off = n * 256 + (((kg >> 1) ^ (n & 7)) << 4) + ((kg & 1) << 3);
        *(uint2*)(smc + hioff + off) = *(const uint2*)hb;
        *(uint2*)(smc + looff + off) = *(const uint2*)lb;
    }
}

/* K=128 one-shot mma core */
__device__ __forceinline__ void mma_k128(uint32_t sb, uint32_t ah, uint32_t al,
        uint32_t bh, uint32_t bl, float acc[4][4][4], int warpM, int warpN, int lane)
{
#pragma unroll
    for (int ks = 0; ks < 8; ks++) {
        uint32_t Bh[4][2], Bl[4][2];
        const int cb = ks * 2 + ((lane >> 3) & 1);
#pragma unroll
        for (int nt = 0; nt < 4; nt++) {
            int row = warpN * 32 + nt * 8 + (lane & 7);
            uint32_t off = row * 256 + ((cb ^ (row & 7)) << 4);
            ldsm_x2(sb + bh + off, Bh[nt][0], Bh[nt][1]);
            ldsm_x2(sb + bl + off, Bl[nt][0], Bl[nt][1]);
        }
        const int ca = ks * 2 + (lane >> 4);
#pragma unroll
        for (int mt = 0; mt < 4; mt++) {
            int row = warpM * 64 + mt * 16 + (lane & 15);
            uint32_t off = row * 256 + ((ca ^ (row & 7)) << 4);
            uint32_t Ah[4], Al[4];
            ldsm_x4(sb + ah + off, Ah[0], Ah[1], Ah[2], Ah[3]);
            ldsm_x4(sb + al + off, Al[0], Al[1], Al[2], Al[3]);
#pragma unroll
            for (int nt = 0; nt < 4; nt++) {
                mma_bf16(acc[mt][nt], Ah, Bh[nt]);
                mma_bf16(acc[mt][nt], Al, Bh[nt]);
                mma_bf16(acc[mt][nt], Ah, Bl[nt]);
            }
        }
    }
}

#define T32K 32768u

/* ---------------- generic C = A@B (+bias) via HMMA, K=128 ---------------- */
__global__ void __launch_bounds__(256) lin_mma(const float* __restrict__ A,
        const float* __restrict__ B, const float* __restrict__ bias,
        float* __restrict__ C, int N)
{
    extern __shared__ char smc[];
    const uint32_t sb = smem_u32(smc);
    const int tid = threadIdx.x, wid = tid >> 5, lane = tid & 31;
    const int warpM = wid >> 2, warpN = wid & 3;
    const int m0 = blockIdx.x * 128, n0 = blockIdx.y * 128;

    load_split_rowk(smc, 0, T32K, A + (long)m0 * 128, 128, tid);
    load_split_coln(smc, 2 * T32K, 3 * T32K, B + n0, N, tid);
    __syncthreads();

    float acc[4][4][4] = {};
    mma_k128(sb, 0, T32K, 2 * T32K, 3 * T32K, acc, warpM, warpN, lane);

    const int gr = lane >> 2, idx = lane & 3;
#pragma unroll
    for (int mt = 0; mt < 4; mt++) {
        int r0 = m0 + warpM * 64 + mt * 16 + gr;
#pragma unroll
        for (int nt = 0; nt < 4; nt++) {
            int col = n0 + warpN * 32 + nt * 8 + 2 * idx;
            float b0 = bias ? bias[col] : 0.f;
            float b1 = bias ? bias[col + 1] : 0.f;
            *(float2*)&C[(long)r0 * N + col] =
                make_float2(acc[mt][nt][0] + b0, acc[mt][nt][1] + b1);
            *(float2*)&C[(long)(r0 + 8) * N + col] =
                make_float2(acc[mt][nt][2] + b0, acc[mt][nt][3] + b1);
        }
    }
}

/* ---------------- per-edge transform, transposed-split output ---------------- */
__global__ void __launch_bounds__(256) pe_mma(const float* __restrict__ h,
                                              const float* __restrict__ Wmsg)
{
    extern __shared__ char smc[];
    const uint32_t sb = smem_u32(smc);
    const int tid = threadIdx.x, wid = tid >> 5, lane = tid & 31;
    const int warpM = wid >> 2, warpN = wid & 3;
    const int s0 = blockIdx.x * 128, e = blockIdx.y;

    load_split_rowk(smc, 0, T32K, h + (long)s0 * 128, 128, tid);
    load_split_coln(smc, 2 * T32K, 3 * T32K, Wmsg + (long)e * 16384, 128, tid);
    __syncthreads();

    float acc[4][4][4] = {};
    mma_k128(sb, 0, T32K, 2 * T32K, 3 * T32K, acc, warpM, warpN, lane);

    __syncthreads();
    float* tb = (float*)smc;                      /* [128 d][132] */
    const int gr = lane >> 2, idx = lane & 3;
#pragma unroll
    for (int mt = 0; mt < 4; mt++) {
        int sr = warpM * 64 + mt * 16 + gr;
#pragma unroll
        for (int nt = 0; nt < 4; nt++) {
            int d = warpN * 32 + nt * 8 + 2 * idx;
            tb[d * 132 + sr]           = acc[mt][nt][0];
            tb[(d + 1) * 132 + sr]     = acc[mt][nt][1];
            tb[d * 132 + sr + 8]       = acc[mt][nt][2];
            tb[(d + 1) * 132 + sr + 8] = acc[mt][nt][3];
        }
    }
    __syncthreads();
#pragma unroll
    for (int i = 0; i < 16; i++) {
        int lin = i * 256 + tid;
        int d = lin >> 5, c4 = lin & 31;
        int s = c4 * 4;
        float4 v = *(const float4*)&tb[d * 132 + s];
        __align__(8) __nv_bfloat16 hb[4], lb[4];
        split4(v, hb, lb);
        long o = (long)d * K_BIG + (long)e * 2048 + s0 + s;
        *(uint2*)&g_Pt_hi[o] = *(const uint2*)hb;
        *(uint2*)&g_Pt_lo[o] = *(const uint2*)lb;
    }
}

/* ---------------- readout NT ---------------- */
__global__ void __launch_bounds__(256) nt_mma(const float* __restrict__ hA,
        const float* __restrict__ h, float* __restrict__ C)
{
    extern __shared__ char smc[];
    const uint32_t sb = smem_u32(smc);
    const int tid = threadIdx.x, wid = tid >> 5, lane = tid & 31;
    const int warpM = wid >> 2, warpN = wid & 3;
    const int i0 = blockIdx.x * 128, j0 = blockIdx.y * 128;

    load_split_rowk(smc, 0, T32K, hA + (long)i0 * 128, 128, tid);
    load_split_rowk(smc, 2 * T32K, 3 * T32K, h + (long)j0 * 128, 128, tid);
    __syncthreads();

    float acc[4][4][4] = {};
    mma_k128(sb, 0, T32K, 2 * T32K, 3 * T32K, acc, warpM, warpN, lane);

    const int gr = lane >> 2, idx = lane & 3;
#pragma unroll
    for (int mt = 0; mt < 4; mt++) {
        int r0 = i0 + warpM * 64 + mt * 16 + gr;
#pragma unroll
        for (int nt = 0; nt < 4; nt++) {
            int col = j0 + warpN * 32 + nt * 8 + 2 * idx;
            *(float2*)&C[(long)r0 * N_NODES + col] = make_float2(acc[mt][nt][0], acc[mt][nt][1]);
            *(float2*)&C[(long)(r0 + 8) * N_NODES + col] = make_float2(acc[mt][nt][2], acc[mt][nt][3]);
        }
    }
}

/* =============== one-time edge transpose+split (coalesced writes) =============== */
__global__ void edge_split_kernel(const float* __restrict__ edge)
{
    __shared__ float sm[64][133];
    const int s0 = blockIdx.x * 64, t0 = blockIdx.y * 16;
    const int tid = threadIdx.x;
#pragma unroll
    for (int it = 0; it < 8; it++) {
        int lin = it * 256 + tid;
        int s_l = lin >> 5, f4 = lin & 31;
        float4 v = *(const float4*)&edge[(long)(s0 + s_l) * K_BIG + t0 * 8 + f4 * 4];
        sm[s_l][f4 * 4 + 0] = v.x; sm[s_l][f4 * 4 + 1] = v.y;
        sm[s_l][f4 * 4 + 2] = v.z; sm[s_l][f4 * 4 + 3] = v.w;
    }
    __syncthreads();
#pragma unroll
    for (int it = 0; it < 4; it++) {
        int lin = it * 256 + tid;
        int sc  = lin & 7;
        int e   = (lin >> 3) & 7;
        int t_l = lin >> 6;
        __align__(16) __nv_bfloat16 hb[8], lb[8];
#pragma unroll
        for (int j = 0; j < 8; j++) {
            float f = sm[sc * 8 + j][t_l * 8 + e];
            __nv_bfloat16 h = __float2bfloat16(f);
            hb[j] = h;
            lb[j] = __float2bfloat16(f - __bfloat162float(h));
        }
        long o = (long)(t0 + t_l) * K_BIG + (long)e * 2048 + s0 + sc * 8;
        *(uint4*)&g_edgeK_hi[o] = *(const uint4*)hb;
        *(uint4*)&g_edgeK_lo[o] = *(const uint4*)lb;
    }
}

/* =============== big message GEMM (pipelined HMMA, R5 inner loop) =============== */
#define MTILE_B 8192u
#define MSTAGE_B 32768u

__global__ void __launch_bounds__(256, 2) msg_mma_kernel()
{
    extern __shared__ char smc[];
    const uint32_t sb = smem_u32(smc);
    const int tid = threadIdx.x;
    const int wid = tid >> 5, lane = tid & 31;
    const int warpM = wid >> 2, warpN = wid & 3;
    const int t0 = blockIdx.x * 128;
    const int e = blockIdx.y, sh = blockIdx.z;
    const long koff = (long)e * 2048 + sh * 1024;

    const __nv_bfloat16* __restrict__ bAh = g_edgeK_hi + (long)t0 * K_BIG + koff;
    const __nv_bfloat16* __restrict__ bAl = g_edgeK_lo + (long)t0 * K_BIG + koff;
    const __nv_bfloat16* __restrict__ bBh = g_Pt_hi + koff;
    const __nv_bfloat16* __restrict__ bBl = g_Pt_lo + koff;

    float acc[4][4][4] = {};

    auto issue = [&](int chunk, int st) {
        const int kofs = chunk * 32;
        const __nv_bfloat16* srcs[4] = { bAh + kofs, bAl + kofs, bBh + kofs, bBl + kofs };
        const uint32_t stage = sb + st * MSTAGE_B;
#pragma unroll
        for (int j = 0; j < 4; j++) {
#pragma unroll
            for (int it = 0; it < 2; it++) {
                int seg = it * 256 + tid;
                int row = seg >> 2, c = seg & 3;
                uint32_t saddr = stage + j * MTILE_B + row * 64 +
                                 ((c ^ ((row >> 1) & 3)) << 4);
                cp_async16(saddr, srcs[j] + (long)row * K_BIG + c * 8);
            }
        }
    };

    issue(0, 0); CP_COMMIT();
    issue(1, 1); CP_COMMIT();
    issue(2, 2); CP_COMMIT();

    for (int chunk = 0; chunk < 32; chunk++) {
        CP_WAIT2();
        __syncthreads();
        const uint32_t stage = sb + (chunk % 3) * MSTAGE_B;

#pragma unroll
        for (int ks = 0; ks < 2; ks++) {
            uint32_t Bh[4][2], Bl[4][2];
            const int cb = ks * 2 + ((lane >> 3) & 1);
#pragma unroll
            for (int nt = 0; nt < 4; nt++) {
                int row = warpN * 32 + nt * 8 + (lane & 7);
                uint32_t off = row * 64 + ((cb ^ ((row >> 1) & 3)) << 4);
                ldsm_x2(stage + 2 * MTILE_B + off, Bh[nt][0], Bh[nt][1]);
                ldsm_x2(stage + 3 * MTILE_B + off, Bl[nt][0], Bl[nt][1]);
            }
            const int ca = ks * 2 + (lane >> 4);
#pragma unroll
            for (int mt = 0; mt < 4; mt++) {
                int row = warpM * 64 + mt * 16 + (lane & 15);
                uint32_t off = row * 64 + ((ca ^ ((row >> 1) & 3)) << 4);
                uint32_t Ah[4], Al[4];
                ldsm_x4(stage + off, Ah[0], Ah[1], Ah[2], Ah[3]);
                ldsm_x4(stage + MTILE_B + off, Al[0], Al[1], Al[2], Al[3]);
#pragma unroll
                for (int nt = 0; nt < 4; nt++) {
                    mma_bf16(acc[mt][nt], Ah, Bh[nt]);
                    mma_bf16(acc[mt][nt], Al, Bh[nt]);
                    mma_bf16(acc[mt][nt], Ah, Bl[nt]);
                }
            }
        }
        __syncthreads();
        if (chunk + 3 < 32) issue(chunk + 3, chunk % 3);
        CP_COMMIT();
    }

    const int gr = lane >> 2, idx = lane & 3;
    const long pbase = (long)(e + 8 * sh) * N_NODES * D_DIM;
#pragma unroll
    for (int mt = 0; mt < 4; mt++) {
        int r0 = t0 + warpM * 64 + mt * 16 + gr;
#pragma unroll
        for (int nt = 0; nt < 4; nt++) {
            int col = warpN * 32 + nt * 8 + 2 * idx;
            store_split2(g_part_hi, g_part_lo, pbase + (long)r0 * D_DIM + col,
                         acc[mt][nt][0], acc[mt][nt][1]);
            store_split2(g_part_hi, g_part_lo, pbase + (long)(r0 + 8) * D_DIM + col,
                         acc[mt][nt][2], acc[mt][nt][3]);
        }
    }
}

/* ---------------- reduce 16 bf16-split partials + bias (8-wide) ---------------- */
__global__ void reduce_bias(const float* __restrict__ bias)
{
    long idx = ((long)blockIdx.x * 256 + threadIdx.x) * 8;   /* < 262144 */
    int d0 = (int)(idx & 127);
    float s[8];
#pragma unroll
    for (int j = 0; j < 8; j++) s[j] = bias[d0 + j];
#pragma unroll
    for (int p = 0; p < 16; p++) {
        uint4 h4 = *(const uint4*)&g_part_hi[(long)p * 262144 + idx];
        uint4 l4 = *(const uint4*)&g_part_lo[(long)p * 262144 + idx];
        const __nv_bfloat162* hp = (const __nv_bfloat162*)&h4;
        const __nv_bfloat162* lp = (const __nv_bfloat162*)&l4;
#pragma unroll
        for (int q = 0; q < 4; q++) {
            s[2 * q + 0] += __bfloat162float(hp[q].x) + __bfloat162float(lp[q].x);
            s[2 * q + 1] += __bfloat162float(hp[q].y) + __bfloat162float(lp[q].y);
        }
    }
    *(float4*)&g_scratch[OFF_MSG + idx]     = make_float4(s[0], s[1], s[2], s[3]);
    *(float4*)&g_scratch[OFF_MSG + idx + 4] = make_float4(s[4], s[5], s[6], s[7]);
}

/* ---------------- GRU elementwise update ---------------- */
__global__ void gru_kernel(int cur)
{
    int idx = blockIdx.x * 256 + threadIdx.x;
    int i = idx >> 7, d = idx & 127;
    const float* __restrict__ gi = g_scratch + OFF_GI;
    const float* __restrict__ gh = g_scratch + OFF_GH;
    const float* __restrict__ h  = g_scratch + (cur ? OFF_H1 : OFF_H0);
    float* __restrict__ ho = g_scratch + (cur ? OFF_H0 : OFF_H1);

    long base = (long)i * 384 + d;
    float ir = gi[base], iz = gi[base + 128], inn = gi[base + 256];
    float hr = gh[base], hz = gh[base + 128], hn  = gh[base + 256];
    float hv = h[idx];
    float r = 1.f / (1.f + expf(-(ir + hr)));
    float z = 1.f / (1.f + expf(-(iz + hz)));
    float n = tanhf(inn + r * hn);
    ho[idx] = (1.f - z) * n + z * hv;
}

/* ---------------- launcher (two-stream fork/join graph) ---------------- */
extern "C" void kernel_launch(void* const* d_in, const int* in_sizes, int n_in,
                              void* d_out, int out_size)
{
    const float* node = (const float*)d_in[0];
    const float* edge = (const float*)d_in[1];
    const float* Wmsg = (const float*)d_in[2];
    const float* bmsg = (const float*)d_in[3];
    const float* Wi   = (const float*)d_in[4];
    const float* Wh   = (const float*)d_in[5];
    const float* bgru = (const float*)d_in[6];
    const float* Aro  = (const float*)d_in[7];
    float* out = (float*)d_out;

    float* scratch = nullptr;
    cudaGetSymbolAddress((void**)&scratch, g_scratch);
    float* H0  = scratch + OFF_H0;
    float* H1  = scratch + OFF_H1;
    float* MSG = scratch + OFF_MSG;
    float* GI  = scratch + OFF_GI;
    float* GH  = scratch + OFF_GH;
    float* HA  = scratch + OFF_HA;

    static cudaStream_t s1 = nullptr;
    static cudaEvent_t evH = nullptr, evGH = nullptr, evE = nullptr;
    if (!s1) {
        cudaStreamCreateWithFlags(&s1, cudaStreamNonBlocking);
        cudaEventCreateWithFlags(&evH, cudaEventDisableTiming);
        cudaEventCreateWithFlags(&evGH, cudaEventDisableTiming);
        cudaEventCreateWithFlags(&evE, cudaEventDisableTiming);
    }

    cudaFuncSetAttribute(msg_mma_kernel, cudaFuncAttributeMaxDynamicSharedMemorySize, 3 * MSTAGE_B);
    cudaFuncSetAttribute(lin_mma, cudaFuncAttributeMaxDynamicSharedMemorySize, 131072);
    cudaFuncSetAttribute(pe_mma, cudaFuncAttributeMaxDynamicSharedMemorySize, 131072);
    cudaFuncSetAttribute(nt_mma, cudaFuncAttributeMaxDynamicSharedMemorySize, 131072);

    cudaMemcpyAsync(H0, node, (size_t)N_NODES * D_DIM * sizeof(float),
                    cudaMemcpyDeviceToDevice);
    cudaEventRecord(evH, 0);                     /* h ready; fork point */

    cudaStreamWaitEvent(s1, evH, 0);
    edge_split_kernel<<<dim3(32, 128), 256, 0, s1>>>(edge);
    cudaEventRecord(evE, s1);

    int cur = 0;
    for (int it = 0; it < GITERS; it++) {
        float* Hc = cur ? H1 : H0;

        pe_mma<<<dim3(16, 8), 256, 131072>>>(Hc, Wmsg);

        if (it > 0) cudaStreamWaitEvent(s1, evH, 0);
        lin_mma<<<dim3(16, 3), 256, 131072, s1>>>(Hc, Wh, nullptr, GH, 384);
        cudaEventRecord(evGH, s1);

        if (it == 0) cudaStreamWaitEvent(0, evE, 0);
        msg_mma_kernel<<<dim3(16, 8, 2), 256, 3 * MSTAGE_B>>>();
        reduce_bias<<<128, 256>>>(bmsg);
        lin_mma<<<dim3(16, 3), 256, 131072>>>(MSG, Wi, bgru, GI, 384);

        cudaStreamWaitEvent(0, evGH, 0);
        gru_kernel<<<1024, 256>>>(cur);
        cudaEventRecord(evH, 0);
        cur ^= 1;
    }
    float* Hf = cur ? H1 : H0;
    lin_mma<<<dim3(16, 1), 256, 131072>>>(Hf, Aro, nullptr, HA, 128);
    nt_mma<<<dim3(16, 16), 256, 131072>>>(HA, Hf, out);
}

// round 8
// speedup vs baseline: 1.1216x; 1.1119x over previous
#include <cuda_runtime.h>
#include <cuda_bf16.h>
#include <math.h>
#include <stdint.h>

#define N_NODES 2048
#define D_DIM   128
#define E_DIM   8
#define GITERS  8
#define K_BIG   (N_NODES * E_DIM)   /* 16384 */

/* ---------------- scratch layout (floats) ---------------- */
#define OFF_H0    0L
#define OFF_H1    262144L
#define OFF_MSG   524288L
#define OFF_GI    786432L                 /* [2048][384] */
#define OFF_GH    1572864L
#define OFF_HA    2359296L
#define SCRATCH_FLOATS 2621440L

__device__ float g_scratch[SCRATCH_FLOATS];

__device__ __align__(16) __nv_bfloat16 g_edgeK_hi[(long)N_NODES * K_BIG];  /* [t][e*2048+s] */
__device__ __align__(16) __nv_bfloat16 g_edgeK_lo[(long)N_NODES * K_BIG];
__device__ __align__(16) __nv_bfloat16 g_Pt_hi[(long)D_DIM * K_BIG];       /* [d][e*2048+s] */
__device__ __align__(16) __nv_bfloat16 g_Pt_lo[(long)D_DIM * K_BIG];
__device__ __align__(16) __nv_bfloat16 g_part_hi[8L * N_NODES * D_DIM];    /* [e][t][d] */
__device__ __align__(16) __nv_bfloat16 g_part_lo[8L * N_NODES * D_DIM];

/* ================= helpers ================= */
__device__ __forceinline__ uint32_t smem_u32(const void* p) {
    uint32_t a;
    asm("{ .reg .u64 t; cvta.to.shared.u64 t, %1; cvt.u32.u64 %0, t; }" : "=r"(a) : "l"(p));
    return a;
}
__device__ __forceinline__ void ldsm_x4(uint32_t addr, uint32_t& r0, uint32_t& r1,
                                        uint32_t& r2, uint32_t& r3) {
    asm volatile("ldmatrix.sync.aligned.m8n8.x4.shared.b16 {%0,%1,%2,%3}, [%4];"
                 : "=r"(r0), "=r"(r1), "=r"(r2), "=r"(r3) : "r"(addr));
}
__device__ __forceinline__ void ldsm_x2(uint32_t addr, uint32_t& r0, uint32_t& r1) {
    asm volatile("ldmatrix.sync.aligned.m8n8.x2.shared.b16 {%0,%1}, [%2];"
                 : "=r"(r0), "=r"(r1) : "r"(addr));
}
__device__ __forceinline__ void mma_bf16(float* c, const uint32_t* a, const uint32_t* b) {
    asm volatile("mma.sync.aligned.m16n8k16.row.col.f32.bf16.bf16.f32 "
                 "{%0,%1,%2,%3}, {%4,%5,%6,%7}, {%8,%9}, {%0,%1,%2,%3};"
                 : "+f"(c[0]), "+f"(c[1]), "+f"(c[2]), "+f"(c[3])
                 : "r"(a[0]), "r"(a[1]), "r"(a[2]), "r"(a[3]), "r"(b[0]), "r"(b[1]));
}
__device__ __forceinline__ void cp_async16(uint32_t saddr, const void* gaddr) {
    asm volatile("cp.async.cg.shared.global [%0], [%1], 16;" :: "r"(saddr), "l"(gaddr) : "memory");
}
#define CP_COMMIT() asm volatile("cp.async.commit_group;" ::: "memory")
#define CP_WAIT2()  asm volatile("cp.async.wait_group 2;" ::: "memory")

__device__ __forceinline__ void split4(float4 v, __nv_bfloat16* hb, __nv_bfloat16* lb) {
    float f[4] = { v.x, v.y, v.z, v.w };
#pragma unroll
    for (int j = 0; j < 4; j++) {
        __nv_bfloat16 h = __float2bfloat16(f[j]);
        hb[j] = h;
        lb[j] = __float2bfloat16(f[j] - __bfloat162float(h));
    }
}
__device__ __forceinline__ void store_split2(__nv_bfloat16* hp, __nv_bfloat16* lp,
                                             long off, float x, float y) {
    __nv_bfloat16 hx = __float2bfloat16(x), hy = __float2bfloat16(y);
    __nv_bfloat16 lx = __float2bfloat16(x - __bfloat162float(hx));
    __nv_bfloat16 ly = __float2bfloat16(y - __bfloat162float(hy));
    __nv_bfloat162 hv; hv.x = hx; hv.y = hy;
    __nv_bfloat162 lv; lv.x = lx; lv.y = ly;
    *(__nv_bfloat162*)(hp + off) = hv;
    *(__nv_bfloat162*)(lp + off) = lv;
}

/* fill split smem tile [128 rows][128 k] (256B rows, xor-swizzled) */
__device__ __forceinline__ void load_split_rowk(char* smc, uint32_t hioff, uint32_t looff,
        const float* __restrict__ g, int ldg, int tid)
{
#pragma unroll
    for (int i = 0; i < 16; i++) {
        int lin = i * 256 + tid;
        int row = lin >> 5, c4 = lin & 31;
        float4 v = *(const float4*)&g[(long)row * ldg + c4 * 4];
        __align__(8) __nv_bfloat16 hb[4], lb[4];
        split4(v, hb, lb);
        uint32_t off = row * 256 + (((c4 >> 1) ^ (row & 7)) << 4) + ((c4 & 1) << 3);
        *(uint2*)(smc + hioff + off) = *(const uint2*)hb;
        *(uint2*)(smc + looff + off) = *(const uint2*)lb;
    }
}

/* fill split smem tile Bs[n][k] from B[k][n0+n] fp32 */
__device__ __forceinline__ void load_split_coln(char* smc, uint32_t hioff, uint32_t looff,
        const float* __restrict__ g, int ldg, int tid)
{
    const int n = tid & 127;
#pragma unroll
    for (int i = 0; i < 16; i++) {
        int kg = i * 2 + (tid >> 7);
        float4 v;
        v.x = g[(long)(kg * 4 + 0) * ldg + n];
        v.y = g[(long)(kg * 4 + 1) * ldg + n];
        v.z = g[(long)(kg * 4 + 2) * ldg + n];
        v.w = g[(long)(kg * 4 + 3) * ldg + n];
        __align__(8) __nv_bfloat16 hb[4], lb[4];
        split4(v, hb, lb);
        uint32_t off = n * 256 + (((kg >> 1) ^ (n & 7)) << 4) + ((kg & 1) << 3);
        *(uint2*)(smc + hioff + off) = *(const uint2*)hb;
        *(uint2*)(smc + looff + off) = *(const uint2*)lb;
    }
}

/* K=128 one-shot mma core */
__device__ __forceinline__ void mma_k128(uint32_t sb, uint32_t ah, uint32_t al,
        uint32_t bh, uint32_t bl, float acc[4][4][4], int warpM, int warpN, int lane)
{
#pragma unroll
    for (int ks = 0; ks < 8; ks++) {
        uint32_t Bh[4][2], Bl[4][2];
        const int cb = ks * 2 + ((lane >> 3) & 1);
#pragma unroll
        for (int nt = 0; nt < 4; nt++) {
            int row = warpN * 32 + nt * 8 + (lane & 7);
            uint32_t off = row * 256 + ((cb ^ (row & 7)) << 4);
            ldsm_x2(sb + bh + off, Bh[nt][0], Bh[nt][1]);
            ldsm_x2(sb + bl + off, Bl[nt][0], Bl[nt][1]);
        }
        const int ca = ks * 2 + (lane >> 4);
#pragma unroll
        for (int mt = 0; mt < 4; mt++) {
            int row = warpM * 64 + mt * 16 + (lane & 15);
            uint32_t off = row * 256 + ((ca ^ (row & 7)) << 4);
            uint32_t Ah[4], Al[4];
            ldsm_x4(sb + ah + off, Ah[0], Ah[1], Ah[2], Ah[3]);
            ldsm_x4(sb + al + off, Al[0], Al[1], Al[2], Al[3]);
#pragma unroll
            for (int nt = 0; nt < 4; nt++) {
                mma_bf16(acc[mt][nt], Ah, Bh[nt]);
                mma_bf16(acc[mt][nt], Al, Bh[nt]);
                mma_bf16(acc[mt][nt], Ah, Bl[nt]);
            }
        }
    }
}

#define T32K 32768u

/* ---------------- generic C = A@B (+bias) via HMMA, K=128 ---------------- */
__global__ void __launch_bounds__(256) lin_mma(const float* __restrict__ A,
        const float* __restrict__ B, const float* __restrict__ bias,
        float* __restrict__ C, int N)
{
    extern __shared__ char smc[];
    const uint32_t sb = smem_u32(smc);
    const int tid = threadIdx.x, wid = tid >> 5, lane = tid & 31;
    const int warpM = wid >> 2, warpN = wid & 3;
    const int m0 = blockIdx.x * 128, n0 = blockIdx.y * 128;

    load_split_rowk(smc, 0, T32K, A + (long)m0 * 128, 128, tid);
    load_split_coln(smc, 2 * T32K, 3 * T32K, B + n0, N, tid);
    __syncthreads();

    float acc[4][4][4] = {};
    mma_k128(sb, 0, T32K, 2 * T32K, 3 * T32K, acc, warpM, warpN, lane);

    const int gr = lane >> 2, idx = lane & 3;
#pragma unroll
    for (int mt = 0; mt < 4; mt++) {
        int r0 = m0 + warpM * 64 + mt * 16 + gr;
#pragma unroll
        for (int nt = 0; nt < 4; nt++) {
            int col = n0 + warpN * 32 + nt * 8 + 2 * idx;
            float b0 = bias ? bias[col] : 0.f;
            float b1 = bias ? bias[col + 1] : 0.f;
            *(float2*)&C[(long)r0 * N + col] =
                make_float2(acc[mt][nt][0] + b0, acc[mt][nt][1] + b1);
            *(float2*)&C[(long)(r0 + 8) * N + col] =
                make_float2(acc[mt][nt][2] + b0, acc[mt][nt][3] + b1);
        }
    }
}

/* ---------------- GI and GH in one z-batched launch (N=384) ---------------- */
__global__ void __launch_bounds__(256) lin2_mma(const float* __restrict__ A0,
        const float* __restrict__ A1, const float* __restrict__ B0,
        const float* __restrict__ B1, const float* __restrict__ bias0,
        float* __restrict__ C0, float* __restrict__ C1)
{
    extern __shared__ char smc[];
    const uint32_t sb = smem_u32(smc);
    const int tid = threadIdx.x, wid = tid >> 5, lane = tid & 31;
    const int warpM = wid >> 2, warpN = wid & 3;
    const int m0 = blockIdx.x * 128, n0 = blockIdx.y * 128;
    const int z = blockIdx.z;
    const float* A = z ? A1 : A0;
    const float* B = z ? B1 : B0;
    const float* bias = z ? nullptr : bias0;
    float* C = z ? C1 : C0;

    load_split_rowk(smc, 0, T32K, A + (long)m0 * 128, 128, tid);
    load_split_coln(smc, 2 * T32K, 3 * T32K, B + n0, 384, tid);
    __syncthreads();

    float acc[4][4][4] = {};
    mma_k128(sb, 0, T32K, 2 * T32K, 3 * T32K, acc, warpM, warpN, lane);

    const int gr = lane >> 2, idx = lane & 3;
#pragma unroll
    for (int mt = 0; mt < 4; mt++) {
        int r0 = m0 + warpM * 64 + mt * 16 + gr;
#pragma unroll
        for (int nt = 0; nt < 4; nt++) {
            int col = n0 + warpN * 32 + nt * 8 + 2 * idx;
            float b0 = bias ? bias[col] : 0.f;
            float b1 = bias ? bias[col + 1] : 0.f;
            *(float2*)&C[(long)r0 * 384 + col] =
                make_float2(acc[mt][nt][0] + b0, acc[mt][nt][1] + b1);
            *(float2*)&C[(long)(r0 + 8) * 384 + col] =
                make_float2(acc[mt][nt][2] + b0, acc[mt][nt][3] + b1);
        }
    }
}

/* ---------------- per-edge transform, transposed-split output ---------------- */
__global__ void __launch_bounds__(256) pe_mma(const float* __restrict__ h,
                                              const float* __restrict__ Wmsg)
{
    extern __shared__ char smc[];
    const uint32_t sb = smem_u32(smc);
    const int tid = threadIdx.x, wid = tid >> 5, lane = tid & 31;
    const int warpM = wid >> 2, warpN = wid & 3;
    const int s0 = blockIdx.x * 128, e = blockIdx.y;

    load_split_rowk(smc, 0, T32K, h + (long)s0 * 128, 128, tid);
    load_split_coln(smc, 2 * T32K, 3 * T32K, Wmsg + (long)e * 16384, 128, tid);
    __syncthreads();

    float acc[4][4][4] = {};
    mma_k128(sb, 0, T32K, 2 * T32K, 3 * T32K, acc, warpM, warpN, lane);

    __syncthreads();
    float* tb = (float*)smc;                      /* [128 d][132] */
    const int gr = lane >> 2, idx = lane & 3;
#pragma unroll
    for (int mt = 0; mt < 4; mt++) {
        int sr = warpM * 64 + mt * 16 + gr;
#pragma unroll
        for (int nt = 0; nt < 4; nt++) {
            int d = warpN * 32 + nt * 8 + 2 * idx;
            tb[d * 132 + sr]           = acc[mt][nt][0];
            tb[(d + 1) * 132 + sr]     = acc[mt][nt][1];
            tb[d * 132 + sr + 8]       = acc[mt][nt][2];
            tb[(d + 1) * 132 + sr + 8] = acc[mt][nt][3];
        }
    }
    __syncthreads();
#pragma unroll
    for (int i = 0; i < 16; i++) {
        int lin = i * 256 + tid;
        int d = lin >> 5, c4 = lin & 31;
        int s = c4 * 4;
        float4 v = *(const float4*)&tb[d * 132 + s];
        __align__(8) __nv_bfloat16 hb[4], lb[4];
        split4(v, hb, lb);
        long o = (long)d * K_BIG + (long)e * 2048 + s0 + s;
        *(uint2*)&g_Pt_hi[o] = *(const uint2*)hb;
        *(uint2*)&g_Pt_lo[o] = *(const uint2*)lb;
    }
}

/* ---------------- readout NT ---------------- */
__global__ void __launch_bounds__(256) nt_mma(const float* __restrict__ hA,
        const float* __restrict__ h, float* __restrict__ C)
{
    extern __shared__ char smc[];
    const uint32_t sb = smem_u32(smc);
    const int tid = threadIdx.x, wid = tid >> 5, lane = tid & 31;
    const int warpM = wid >> 2, warpN = wid & 3;
    const int i0 = blockIdx.x * 128, j0 = blockIdx.y * 128;

    load_split_rowk(smc, 0, T32K, hA + (long)i0 * 128, 128, tid);
    load_split_rowk(smc, 2 * T32K, 3 * T32K, h + (long)j0 * 128, 128, tid);
    __syncthreads();

    float acc[4][4][4] = {};
    mma_k128(sb, 0, T32K, 2 * T32K, 3 * T32K, acc, warpM, warpN, lane);

    const int gr = lane >> 2, idx = lane & 3;
#pragma unroll
    for (int mt = 0; mt < 4; mt++) {
        int r0 = i0 + warpM * 64 + mt * 16 + gr;
#pragma unroll
        for (int nt = 0; nt < 4; nt++) {
            int col = j0 + warpN * 32 + nt * 8 + 2 * idx;
            *(float2*)&C[(long)r0 * N_NODES + col] = make_float2(acc[mt][nt][0], acc[mt][nt][1]);
            *(float2*)&C[(long)(r0 + 8) * N_NODES + col] = make_float2(acc[mt][nt][2], acc[mt][nt][3]);
        }
    }
}

/* =============== one-time edge transpose+split (coalesced writes) =============== */
__global__ void edge_split_kernel(const float* __restrict__ edge)
{
    __shared__ float sm[64][133];
    const int s0 = blockIdx.x * 64, t0 = blockIdx.y * 16;
    const int tid = threadIdx.x;
#pragma unroll
    for (int it = 0; it < 8; it++) {
        int lin = it * 256 + tid;
        int s_l = lin >> 5, f4 = lin & 31;
        float4 v = *(const float4*)&edge[(long)(s0 + s_l) * K_BIG + t0 * 8 + f4 * 4];
        sm[s_l][f4 * 4 + 0] = v.x; sm[s_l][f4 * 4 + 1] = v.y;
        sm[s_l][f4 * 4 + 2] = v.z; sm[s_l][f4 * 4 + 3] = v.w;
    }
    __syncthreads();
#pragma unroll
    for (int it = 0; it < 4; it++) {
        int lin = it * 256 + tid;
        int sc  = lin & 7;
        int e   = (lin >> 3) & 7;
        int t_l = lin >> 6;
        __align__(16) __nv_bfloat16 hb[8], lb[8];
#pragma unroll
        for (int j = 0; j < 8; j++) {
            float f = sm[sc * 8 + j][t_l * 8 + e];
            __nv_bfloat16 h = __float2bfloat16(f);
            hb[j] = h;
            lb[j] = __float2bfloat16(f - __bfloat162float(h));
        }
        long o = (long)(t0 + t_l) * K_BIG + (long)e * 2048 + s0 + sc * 8;
        *(uint4*)&g_edgeK_hi[o] = *(const uint4*)hb;
        *(uint4*)&g_edgeK_lo[o] = *(const uint4*)lb;
    }
}

/* =============== big message GEMM — R3 config (grid 16x8, kchunk 64,
 * 64KB stages, NO occupancy cap) + bf16-split partial epilogue =============== */
#define STAGE_BYTES 65536
#define TILE_B      16384

__global__ void __launch_bounds__(256, 1) msg_mma_kernel()
{
    extern __shared__ char smc[];
    const uint32_t sb = smem_u32(smc);
    const int tid = threadIdx.x;
    const int wid = tid >> 5, lane = tid & 31;
    const int warpM = wid >> 2, warpN = wid & 3;
    const int t0 = blockIdx.x * 128;
    const int e = blockIdx.y;
    const long koff = (long)e * 2048;

    const __nv_bfloat16* __restrict__ bAh = g_edgeK_hi + (long)t0 * K_BIG + koff;
    const __nv_bfloat16* __restrict__ bAl = g_edgeK_lo + (long)t0 * K_BIG + koff;
    const __nv_bfloat16* __restrict__ bBh = g_Pt_hi + koff;
    const __nv_bfloat16* __restrict__ bBl = g_Pt_lo + koff;

    float acc[4][4][4] = {};

    auto issue = [&](int chunk, int st) {
        const int kofs = chunk * 64;
        const __nv_bfloat16* srcs[4] = { bAh + kofs, bAl + kofs, bBh + kofs, bBl + kofs };
        const uint32_t stage = sb + st * STAGE_BYTES;
#pragma unroll
        for (int j = 0; j < 4; j++) {
#pragma unroll
            for (int it = 0; it < 4; it++) {
                int seg = it * 256 + tid;
                int row = seg >> 3, c = seg & 7;
                uint32_t saddr = stage + j * TILE_B + row * 128 + ((c ^ (row & 7)) << 4);
                cp_async16(saddr, srcs[j] + (long)row * K_BIG + c * 8);
            }
        }
    };

    issue(0, 0); CP_COMMIT();
    issue(1, 1); CP_COMMIT();
    issue(2, 2); CP_COMMIT();

    for (int chunk = 0; chunk < 32; chunk++) {
        CP_WAIT2();
        __syncthreads();
        const uint32_t stage = sb + (chunk % 3) * STAGE_BYTES;

#pragma unroll
        for (int ks = 0; ks < 4; ks++) {
            uint32_t Ah[4][4], Al[4][4], Bh[4][2], Bl[4][2];
            const int ra_l = lane & 15, ca = ks * 2 + (lane >> 4);
#pragma unroll
            for (int mt = 0; mt < 4; mt++) {
                int row = warpM * 64 + mt * 16 + ra_l;
                uint32_t off = row * 128 + ((ca ^ (row & 7)) << 4);
                ldsm_x4(stage + off,          Ah[mt][0], Ah[mt][1], Ah[mt][2], Ah[mt][3]);
                ldsm_x4(stage + TILE_B + off, Al[mt][0], Al[mt][1], Al[mt][2], Al[mt][3]);
            }
            const int rb_l = lane & 7, cb = ks * 2 + ((lane >> 3) & 1);
#pragma unroll
            for (int nt = 0; nt < 4; nt++) {
                int row = warpN * 32 + nt * 8 + rb_l;
                uint32_t off = row * 128 + ((cb ^ (row & 7)) << 4);
                ldsm_x2(stage + 2 * TILE_B + off, Bh[nt][0], Bh[nt][1]);
                ldsm_x2(stage + 3 * TILE_B + off, Bl[nt][0], Bl[nt][1]);
            }
#pragma unroll
            for (int mt = 0; mt < 4; mt++)
#pragma unroll
                for (int nt = 0; nt < 4; nt++) {
                    mma_bf16(acc[mt][nt], Ah[mt], Bh[nt]);
                    mma_bf16(acc[mt][nt], Al[mt], Bh[nt]);
                    mma_bf16(acc[mt][nt], Ah[mt], Bl[nt]);
                }
        }
        __syncthreads();
        if (chunk + 3 < 32) issue(chunk + 3, chunk % 3);
        CP_COMMIT();
    }

    /* epilogue: bf16-split partials, 8 e-partials */
    const int gr = lane >> 2, idx = lane & 3;
    const long pbase = (long)e * N_NODES * D_DIM;
#pragma unroll
    for (int mt = 0; mt < 4; mt++) {
        int r0 = t0 + warpM * 64 + mt * 16 + gr;
#pragma unroll
        for (int nt = 0; nt < 4; nt++) {
            int col = warpN * 32 + nt * 8 + 2 * idx;
            store_split2(g_part_hi, g_part_lo, pbase + (long)r0 * D_DIM + col,
                         acc[mt][nt][0], acc[mt][nt][1]);
            store_split2(g_part_hi, g_part_lo, pbase + (long)(r0 + 8) * D_DIM + col,
                         acc[mt][nt][2], acc[mt][nt][3]);
        }
    }
}

/* ---------------- reduce 8 bf16-split partials + bias (8-wide) ---------------- */
__global__ void reduce_bias(const float* __restrict__ bias)
{
    long idx = ((long)blockIdx.x * 256 + threadIdx.x) * 8;   /* < 262144 */
    int d0 = (int)(idx & 127);
    float s[8];
#pragma unroll
    for (int j = 0; j < 8; j++) s[j] = bias[d0 + j];
#pragma unroll
    for (int p = 0; p < 8; p++) {
        uint4 h4 = *(const uint4*)&g_part_hi[(long)p * 262144 + idx];
        uint4 l4 = *(const uint4*)&g_part_lo[(long)p * 262144 + idx];
        const __nv_bfloat162* hp = (const __nv_bfloat162*)&h4;
        const __nv_bfloat162* lp = (const __nv_bfloat162*)&l4;
#pragma unroll
        for (int q = 0; q < 4; q++) {
            s[2 * q + 0] += __bfloat162float(hp[q].x) + __bfloat162float(lp[q].x);
            s[2 * q + 1] += __bfloat162float(hp[q].y) + __bfloat162float(lp[q].y);
        }
    }
    *(float4*)&g_scratch[OFF_MSG + idx]     = make_float4(s[0], s[1], s[2], s[3]);
    *(float4*)&g_scratch[OFF_MSG + idx + 4] = make_float4(s[4], s[5], s[6], s[7]);
}

/* ---------------- GRU elementwise update ---------------- */
__global__ void gru_kernel(int cur)
{
    int idx = blockIdx.x * 256 + threadIdx.x;
    int i = idx >> 7, d = idx & 127;
    const float* __restrict__ gi = g_scratch + OFF_GI;
    const float* __restrict__ gh = g_scratch + OFF_GH;
    const float* __restrict__ h  = g_scratch + (cur ? OFF_H1 : OFF_H0);
    float* __restrict__ ho = g_scratch + (cur ? OFF_H0 : OFF_H1);

    long base = (long)i * 384 + d;
    float ir = gi[base], iz = gi[base + 128], inn = gi[base + 256];
    float hr = gh[base], hz = gh[base + 128], hn  = gh[base + 256];
    float hv = h[idx];
    float r = 1.f / (1.f + expf(-(ir + hr)));
    float z = 1.f / (1.f + expf(-(iz + hz)));
    float n = tanhf(inn + r * hn);
    ho[idx] = (1.f - z) * n + z * hv;
}

/* ---------------- launcher (single stream) ---------------- */
extern "C" void kernel_launch(void* const* d_in, const int* in_sizes, int n_in,
                              void* d_out, int out_size)
{
    const float* node = (const float*)d_in[0];
    const float* edge = (const float*)d_in[1];
    const float* Wmsg = (const float*)d_in[2];
    const float* bmsg = (const float*)d_in[3];
    const float* Wi   = (const float*)d_in[4];
    const float* Wh   = (const float*)d_in[5];
    const float* bgru = (const float*)d_in[6];
    const float* Aro  = (const float*)d_in[7];
    float* out = (float*)d_out;

    float* scratch = nullptr;
    cudaGetSymbolAddress((void**)&scratch, g_scratch);
    float* H0  = scratch + OFF_H0;
    float* H1  = scratch + OFF_H1;
    float* MSG = scratch + OFF_MSG;
    float* GI  = scratch + OFF_GI;
    float* GH  = scratch + OFF_GH;
    float* HA  = scratch + OFF_HA;

    cudaFuncSetAttribute(msg_mma_kernel, cudaFuncAttributeMaxDynamicSharedMemorySize, 3 * STAGE_BYTES);
    cudaFuncSetAttribute(lin_mma, cudaFuncAttributeMaxDynamicSharedMemorySize, 131072);
    cudaFuncSetAttribute(lin2_mma, cudaFuncAttributeMaxDynamicSharedMemorySize, 131072);
    cudaFuncSetAttribute(pe_mma, cudaFuncAttributeMaxDynamicSharedMemorySize, 131072);
    cudaFuncSetAttribute(nt_mma, cudaFuncAttributeMaxDynamicSharedMemorySize, 131072);

    cudaMemcpyAsync(H0, node, (size_t)N_NODES * D_DIM * sizeof(float),
                    cudaMemcpyDeviceToDevice);

    edge_split_kernel<<<dim3(32, 128), 256>>>(edge);

    int cur = 0;
    for (int it = 0; it < GITERS; it++) {
        float* Hc = cur ? H1 : H0;
        pe_mma<<<dim3(16, 8), 256, 131072>>>(Hc, Wmsg);
        msg_mma_kernel<<<dim3(16, 8), 256, 3 * STAGE_BYTES>>>();
        reduce_bias<<<128, 256>>>(bmsg);
        lin2_mma<<<dim3(16, 3, 2), 256, 131072>>>(MSG, Hc, Wi, Wh, bgru, GI, GH);
        gru_kernel<<<1024, 256>>>(cur);
        cur ^= 1;
    }
    float* Hf = cur ? H1 : H0;
    lin_mma<<<dim3(16, 1), 256, 131072>>>(Hf, Aro, nullptr, HA, 128);
    nt_mma<<<dim3(16, 16), 256, 131072>>>(HA, Hf, out);
}

// round 11
// speedup vs baseline: 1.1446x; 1.0205x over previous
#include <cuda_runtime.h>
#include <cuda_bf16.h>
#include <math.h>
#include <stdint.h>

#define N_NODES 2048
#define D_DIM   128
#define E_DIM   8
#define GITERS  8
#define K_BIG   (N_NODES * E_DIM)   /* 16384 */

/* ---------------- scratch layout (floats) ---------------- */
#define OFF_H0    0L
#define OFF_H1    262144L
#define OFF_MSG   524288L
#define OFF_GI    786432L                 /* [2048][384] */
#define OFF_GH    1572864L
#define OFF_HA    2359296L
#define SCRATCH_FLOATS 2621440L

__device__ float g_scratch[SCRATCH_FLOATS];

__device__ __align__(16) __nv_bfloat16 g_edgeK_hi[(long)N_NODES * K_BIG];  /* [t][e*2048+s] */
__device__ __align__(16) __nv_bfloat16 g_edgeK_lo[(long)N_NODES * K_BIG];
__device__ __align__(16) __nv_bfloat16 g_Pt_hi[(long)D_DIM * K_BIG];       /* [d][e*2048+s] */
__device__ __align__(16) __nv_bfloat16 g_Pt_lo[(long)D_DIM * K_BIG];
__device__ __align__(16) __nv_bfloat16 g_part_hi[8L * N_NODES * D_DIM];    /* [e][t][d] */
__device__ __align__(16) __nv_bfloat16 g_part_lo[8L * N_NODES * D_DIM];

/* ================= helpers ================= */
__device__ __forceinline__ uint32_t smem_u32(const void* p) {
    uint32_t a;
    asm("{ .reg .u64 t; cvta.to.shared.u64 t, %1; cvt.u32.u64 %0, t; }" : "=r"(a) : "l"(p));
    return a;
}
__device__ __forceinline__ void ldsm_x4(uint32_t addr, uint32_t& r0, uint32_t& r1,
                                        uint32_t& r2, uint32_t& r3) {
    asm volatile("ldmatrix.sync.aligned.m8n8.x4.shared.b16 {%0,%1,%2,%3}, [%4];"
                 : "=r"(r0), "=r"(r1), "=r"(r2), "=r"(r3) : "r"(addr));
}
__device__ __forceinline__ void ldsm_x2(uint32_t addr, uint32_t& r0, uint32_t& r1) {
    asm volatile("ldmatrix.sync.aligned.m8n8.x2.shared.b16 {%0,%1}, [%2];"
                 : "=r"(r0), "=r"(r1) : "r"(addr));
}
__device__ __forceinline__ void mma_bf16(float* c, const uint32_t* a, const uint32_t* b) {
    asm volatile("mma.sync.aligned.m16n8k16.row.col.f32.bf16.bf16.f32 "
                 "{%0,%1,%2,%3}, {%4,%5,%6,%7}, {%8,%9}, {%0,%1,%2,%3};"
                 : "+f"(c[0]), "+f"(c[1]), "+f"(c[2]), "+f"(c[3])
                 : "r"(a[0]), "r"(a[1]), "r"(a[2]), "r"(a[3]), "r"(b[0]), "r"(b[1]));
}
__device__ __forceinline__ void cp_async16(uint32_t saddr, const void* gaddr) {
    asm volatile("cp.async.cg.shared.global [%0], [%1], 16;" :: "r"(saddr), "l"(gaddr) : "memory");
}
#define CP_COMMIT() asm volatile("cp.async.commit_group;" ::: "memory")
#define CP_WAIT2()  asm volatile("cp.async.wait_group 2;" ::: "memory")

__device__ __forceinline__ void split4(float4 v, __nv_bfloat16* hb, __nv_bfloat16* lb) {
    float f[4] = { v.x, v.y, v.z, v.w };
#pragma unroll
    for (int j = 0; j < 4; j++) {
        __nv_bfloat16 h = __float2bfloat16(f[j]);
        hb[j] = h;
        lb[j] = __float2bfloat16(f[j] - __bfloat162float(h));
    }
}
__device__ __forceinline__ void store_split2(__nv_bfloat16* hp, __nv_bfloat16* lp,
                                             long off, float x, float y) {
    __nv_bfloat16 hx = __float2bfloat16(x), hy = __float2bfloat16(y);
    __nv_bfloat16 lx = __float2bfloat16(x - __bfloat162float(hx));
    __nv_bfloat16 ly = __float2bfloat16(y - __bfloat162float(hy));
    __nv_bfloat162 hv; hv.x = hx; hv.y = hy;
    __nv_bfloat162 lv; lv.x = lx; lv.y = ly;
    *(__nv_bfloat162*)(hp + off) = hv;
    *(__nv_bfloat162*)(lp + off) = lv;
}

/* fill split smem tile [128 rows][128 k] (256B rows, xor-swizzled) */
__device__ __forceinline__ void load_split_rowk(char* smc, uint32_t hioff, uint32_t looff,
        const float* __restrict__ g, int ldg, int tid)
{
#pragma unroll
    for (int i = 0; i < 16; i++) {
        int lin = i * 256 + tid;
        int row = lin >> 5, c4 = lin & 31;
        float4 v = *(const float4*)&g[(long)row * ldg + c4 * 4];
        __align__(8) __nv_bfloat16 hb[4], lb[4];
        split4(v, hb, lb);
        uint32_t off = row * 256 + (((c4 >> 1) ^ (row & 7)) << 4) + ((c4 & 1) << 3);
        *(uint2*)(smc + hioff + off) = *(const uint2*)hb;
        *(uint2*)(smc + looff + off) = *(const uint2*)lb;
    }
}

/* fill split smem tile Bs[n][k] from B[k][n0+n] fp32 */
__device__ __forceinline__ void load_split_coln(char* smc, uint32_t hioff, uint32_t looff,
        const float* __restrict__ g, int ldg, int tid)
{
    const int n = tid & 127;
#pragma unroll
    for (int i = 0; i < 16; i++) {
        int kg = i * 2 + (tid >> 7);
        float4 v;
        v.x = g[(long)(kg * 4 + 0) * ldg + n];
        v.y = g[(long)(kg * 4 + 1) * ldg + n];
        v.z = g[(long)(kg * 4 + 2) * ldg + n];
        v.w = g[(long)(kg * 4 + 3) * ldg + n];
        __align__(8) __nv_bfloat16 hb[4], lb[4];
        split4(v, hb, lb);
        uint32_t off = n * 256 + (((kg >> 1) ^ (n & 7)) << 4) + ((kg & 1) << 3);
        *(uint2*)(smc + hioff + off) = *(const uint2*)hb;
        *(uint2*)(smc + looff + off) = *(const uint2*)lb;
    }
}

/* K=128 one-shot mma core */
__device__ __forceinline__ void mma_k128(uint32_t sb, uint32_t ah, uint32_t al,
        uint32_t bh, uint32_t bl, float acc[4][4][4], int warpM, int warpN, int lane)
{
#pragma unroll
    for (int ks = 0; ks < 8; ks++) {
        uint32_t Bh[4][2], Bl[4][2];
        const int cb = ks * 2 + ((lane >> 3) & 1);
#pragma unroll
        for (int nt = 0; nt < 4; nt++) {
            int row = warpN * 32 + nt * 8 + (lane & 7);
            uint32_t off = row * 256 + ((cb ^ (row & 7)) << 4);
            ldsm_x2(sb + bh + off, Bh[nt][0], Bh[nt][1]);
            ldsm_x2(sb + bl + off, Bl[nt][0], Bl[nt][1]);
        }
        const int ca = ks * 2 + (lane >> 4);
#pragma unroll
        for (int mt = 0; mt < 4; mt++) {
            int row = warpM * 64 + mt * 16 + (lane & 15);
            uint32_t off = row * 256 + ((ca ^ (row & 7)) << 4);
            uint32_t Ah[4], Al[4];
            ldsm_x4(sb + ah + off, Ah[0], Ah[1], Ah[2], Ah[3]);
            ldsm_x4(sb + al + off, Al[0], Al[1], Al[2], Al[3]);
#pragma unroll
            for (int nt = 0; nt < 4; nt++) {
                mma_bf16(acc[mt][nt], Ah, Bh[nt]);
                mma_bf16(acc[mt][nt], Al, Bh[nt]);
                mma_bf16(acc[mt][nt], Ah, Bl[nt]);
            }
        }
    }
}

#define T32K 32768u

/* ---------------- generic C = A@B (+bias) via HMMA, K=128 ---------------- */
__global__ void __launch_bounds__(256) lin_mma(const float* __restrict__ A,
        const float* __restrict__ B, const float* __restrict__ bias,
        float* __restrict__ C, int N)
{
    extern __shared__ char smc[];
    const uint32_t sb = smem_u32(smc);
    const int tid = threadIdx.x, wid = tid >> 5, lane = tid & 31;
    const int warpM = wid >> 2, warpN = wid & 3;
    const int m0 = blockIdx.x * 128, n0 = blockIdx.y * 128;

    load_split_rowk(smc, 0, T32K, A + (long)m0 * 128, 128, tid);
    load_split_coln(smc, 2 * T32K, 3 * T32K, B + n0, N, tid);
    __syncthreads();

    float acc[4][4][4] = {};
    mma_k128(sb, 0, T32K, 2 * T32K, 3 * T32K, acc, warpM, warpN, lane);

    const int gr = lane >> 2, idx = lane & 3;
#pragma unroll
    for (int mt = 0; mt < 4; mt++) {
        int r0 = m0 + warpM * 64 + mt * 16 + gr;
#pragma unroll
        for (int nt = 0; nt < 4; nt++) {
            int col = n0 + warpN * 32 + nt * 8 + 2 * idx;
            float b0 = bias ? bias[col] : 0.f;
            float b1 = bias ? bias[col + 1] : 0.f;
            *(float2*)&C[(long)r0 * N + col] =
                make_float2(acc[mt][nt][0] + b0, acc[mt][nt][1] + b1);
            *(float2*)&C[(long)(r0 + 8) * N + col] =
                make_float2(acc[mt][nt][2] + b0, acc[mt][nt][3] + b1);
        }
    }
}

/* ---------------- GI and GH in one z-batched launch (N=384) ---------------- */
__global__ void __launch_bounds__(256) lin2_mma(const float* __restrict__ A0,
        const float* __restrict__ A1, const float* __restrict__ B0,
        const float* __restrict__ B1, const float* __restrict__ bias0,
        float* __restrict__ C0, float* __restrict__ C1)
{
    extern __shared__ char smc[];
    const uint32_t sb = smem_u32(smc);
    const int tid = threadIdx.x, wid = tid >> 5, lane = tid & 31;
    const int warpM = wid >> 2, warpN = wid & 3;
    const int m0 = blockIdx.x * 128, n0 = blockIdx.y * 128;
    const int z = blockIdx.z;
    const float* A = z ? A1 : A0;
    const float* B = z ? B1 : B0;
    const float* bias = z ? nullptr : bias0;
    float* C = z ? C1 : C0;

    load_split_rowk(smc, 0, T32K, A + (long)m0 * 128, 128, tid);
    load_split_coln(smc, 2 * T32K, 3 * T32K, B + n0, 384, tid);
    __syncthreads();

    float acc[4][4][4] = {};
    mma_k128(sb, 0, T32K, 2 * T32K, 3 * T32K, acc, warpM, warpN, lane);

    const int gr = lane >> 2, idx = lane & 3;
#pragma unroll
    for (int mt = 0; mt < 4; mt++) {
        int r0 = m0 + warpM * 64 + mt * 16 + gr;
#pragma unroll
        for (int nt = 0; nt < 4; nt++) {
            int col = n0 + warpN * 32 + nt * 8 + 2 * idx;
            float b0 = bias ? bias[col] : 0.f;
            float b1 = bias ? bias[col + 1] : 0.f;
            *(float2*)&C[(long)r0 * 384 + col] =
                make_float2(acc[mt][nt][0] + b0, acc[mt][nt][1] + b1);
            *(float2*)&C[(long)(r0 + 8) * 384 + col] =
                make_float2(acc[mt][nt][2] + b0, acc[mt][nt][3] + b1);
        }
    }
}

/* ---------------- per-edge transform, transposed-split output ---------------- */
__global__ void __launch_bounds__(256) pe_mma(const float* __restrict__ h,
                                              const float* __restrict__ Wmsg)
{
    extern __shared__ char smc[];
    const uint32_t sb = smem_u32(smc);
    const int tid = threadIdx.x, wid = tid >> 5, lane = tid & 31;
    const int warpM = wid >> 2, warpN = wid & 3;
    const int s0 = blockIdx.x * 128, e = blockIdx.y;

    load_split_rowk(smc, 0, T32K, h + (long)s0 * 128, 128, tid);
    load_split_coln(smc, 2 * T32K, 3 * T32K, Wmsg + (long)e * 16384, 128, tid);
    __syncthreads();

    float acc[4][4][4] = {};
    mma_k128(sb, 0, T32K, 2 * T32K, 3 * T32K, acc, warpM, warpN, lane);

    __syncthreads();
    float* tb = (float*)smc;                      /* [128 d][132] */
    const int gr = lane >> 2, idx = lane & 3;
#pragma unroll
    for (int mt = 0; mt < 4; mt++) {
        int sr = warpM * 64 + mt * 16 + gr;
#pragma unroll
        for (int nt = 0; nt < 4; nt++) {
            int d = warpN * 32 + nt * 8 + 2 * idx;
            tb[d * 132 + sr]           = acc[mt][nt][0];
            tb[(d + 1) * 132 + sr]     = acc[mt][nt][1];
            tb[d * 132 + sr + 8]       = acc[mt][nt][2];
            tb[(d + 1) * 132 + sr + 8] = acc[mt][nt][3];
        }
    }
    __syncthreads();
#pragma unroll
    for (int i = 0; i < 16; i++) {
        int lin = i * 256 + tid;
        int d = lin >> 5, c4 = lin & 31;
        int s = c4 * 4;
        float4 v = *(const float4*)&tb[d * 132 + s];
        __align__(8) __nv_bfloat16 hb[4], lb[4];
        split4(v, hb, lb);
        long o = (long)d * K_BIG + (long)e * 2048 + s0 + s;
        *(uint2*)&g_Pt_hi[o] = *(const uint2*)hb;
        *(uint2*)&g_Pt_lo[o] = *(const uint2*)lb;
    }
}

/* ---------------- readout NT ---------------- */
__global__ void __launch_bounds__(256) nt_mma(const float* __restrict__ hA,
        const float* __restrict__ h, float* __restrict__ C)
{
    extern __shared__ char smc[];
    const uint32_t sb = smem_u32(smc);
    const int tid = threadIdx.x, wid = tid >> 5, lane = tid & 31;
    const int warpM = wid >> 2, warpN = wid & 3;
    const int i0 = blockIdx.x * 128, j0 = blockIdx.y * 128;

    load_split_rowk(smc, 0, T32K, hA + (long)i0 * 128, 128, tid);
    load_split_rowk(smc, 2 * T32K, 3 * T32K, h + (long)j0 * 128, 128, tid);
    __syncthreads();

    float acc[4][4][4] = {};
    mma_k128(sb, 0, T32K, 2 * T32K, 3 * T32K, acc, warpM, warpN, lane);

    const int gr = lane >> 2, idx = lane & 3;
#pragma unroll
    for (int mt = 0; mt < 4; mt++) {
        int r0 = i0 + warpM * 64 + mt * 16 + gr;
#pragma unroll
        for (int nt = 0; nt < 4; nt++) {
            int col = j0 + warpN * 32 + nt * 8 + 2 * idx;
            *(float2*)&C[(long)r0 * N_NODES + col] = make_float2(acc[mt][nt][0], acc[mt][nt][1]);
            *(float2*)&C[(long)(r0 + 8) * N_NODES + col] = make_float2(acc[mt][nt][2], acc[mt][nt][3]);
        }
    }
}

/* =============== one-time edge transpose+split (coalesced writes) =============== */
__global__ void edge_split_kernel(const float* __restrict__ edge)
{
    __shared__ float sm[64][133];
    const int s0 = blockIdx.x * 64, t0 = blockIdx.y * 16;
    const int tid = threadIdx.x;
#pragma unroll
    for (int it = 0; it < 8; it++) {
        int lin = it * 256 + tid;
        int s_l = lin >> 5, f4 = lin & 31;
        float4 v = *(const float4*)&edge[(long)(s0 + s_l) * K_BIG + t0 * 8 + f4 * 4];
        sm[s_l][f4 * 4 + 0] = v.x; sm[s_l][f4 * 4 + 1] = v.y;
        sm[s_l][f4 * 4 + 2] = v.z; sm[s_l][f4 * 4 + 3] = v.w;
    }
    __syncthreads();
#pragma unroll
    for (int it = 0; it < 4; it++) {
        int lin = it * 256 + tid;
        int sc  = lin & 7;
        int e   = (lin >> 3) & 7;
        int t_l = lin >> 6;
        __align__(16) __nv_bfloat16 hb[8], lb[8];
#pragma unroll
        for (int j = 0; j < 8; j++) {
            float f = sm[sc * 8 + j][t_l * 8 + e];
            __nv_bfloat16 h = __float2bfloat16(f);
            hb[j] = h;
            lb[j] = __float2bfloat16(f - __bfloat162float(h));
        }
        long o = (long)(t0 + t_l) * K_BIG + (long)e * 2048 + s0 + sc * 8;
        *(uint4*)&g_edgeK_hi[o] = *(const uint4*)hb;
        *(uint4*)&g_edgeK_lo[o] = *(const uint4*)lb;
    }
}

/* =============== big message GEMM — R3 config + bf16-split partial epilogue ===== */
#define STAGE_BYTES 65536
#define TILE_B      16384

__global__ void __launch_bounds__(256, 1) msg_mma_kernel()
{
    extern __shared__ char smc[];
    const uint32_t sb = smem_u32(smc);
    const int tid = threadIdx.x;
    const int wid = tid >> 5, lane = tid & 31;
    const int warpM = wid >> 2, warpN = wid & 3;
    const int t0 = blockIdx.x * 128;
    const int e = blockIdx.y;
    const long koff = (long)e * 2048;

    const __nv_bfloat16* __restrict__ bAh = g_edgeK_hi + (long)t0 * K_BIG + koff;
    const __nv_bfloat16* __restrict__ bAl = g_edgeK_lo + (long)t0 * K_BIG + koff;
    const __nv_bfloat16* __restrict__ bBh = g_Pt_hi + koff;
    const __nv_bfloat16* __restrict__ bBl = g_Pt_lo + koff;

    float acc[4][4][4] = {};

    auto issue = [&](int chunk, int st) {
        const int kofs = chunk * 64;
        const __nv_bfloat16* srcs[4] = { bAh + kofs, bAl + kofs, bBh + kofs, bBl + kofs };
        const uint32_t stage = sb + st * STAGE_BYTES;
#pragma unroll
        for (int j = 0; j < 4; j++) {
#pragma unroll
            for (int it = 0; it < 4; it++) {
                int seg = it * 256 + tid;
                int row = seg >> 3, c = seg & 7;
                uint32_t saddr = stage + j * TILE_B + row * 128 + ((c ^ (row & 7)) << 4);
                cp_async16(saddr, srcs[j] + (long)row * K_BIG + c * 8);
            }
        }
    };

    issue(0, 0); CP_COMMIT();
    issue(1, 1); CP_COMMIT();
    issue(2, 2); CP_COMMIT();

    for (int chunk = 0; chunk < 32; chunk++) {
        CP_WAIT2();
        __syncthreads();
        const uint32_t stage = sb + (chunk % 3) * STAGE_BYTES;

#pragma unroll
        for (int ks = 0; ks < 4; ks++) {
            uint32_t Ah[4][4], Al[4][4], Bh[4][2], Bl[4][2];
            const int ra_l = lane & 15, ca = ks * 2 + (lane >> 4);
#pragma unroll
            for (int mt = 0; mt < 4; mt++) {
                int row = warpM * 64 + mt * 16 + ra_l;
                uint32_t off = row * 128 + ((ca ^ (row & 7)) << 4);
                ldsm_x4(stage + off,          Ah[mt][0], Ah[mt][1], Ah[mt][2], Ah[mt][3]);
                ldsm_x4(stage + TILE_B + off, Al[mt][0], Al[mt][1], Al[mt][2], Al[mt][3]);
            }
            const int rb_l = lane & 7, cb = ks * 2 + ((lane >> 3) & 1);
#pragma unroll
            for (int nt = 0; nt < 4; nt++) {
                int row = warpN * 32 + nt * 8 + rb_l;
                uint32_t off = row * 128 + ((cb ^ (row & 7)) << 4);
                ldsm_x2(stage + 2 * TILE_B + off, Bh[nt][0], Bh[nt][1]);
                ldsm_x2(stage + 3 * TILE_B + off, Bl[nt][0], Bl[nt][1]);
            }
#pragma unroll
            for (int mt = 0; mt < 4; mt++)
#pragma unroll
                for (int nt = 0; nt < 4; nt++) {
                    mma_bf16(acc[mt][nt], Ah[mt], Bh[nt]);
                    mma_bf16(acc[mt][nt], Al[mt], Bh[nt]);
                    mma_bf16(acc[mt][nt], Ah[mt], Bl[nt]);
                }
        }
        __syncthreads();
        if (chunk + 3 < 32) issue(chunk + 3, chunk % 3);
        CP_COMMIT();
    }

    const int gr = lane >> 2, idx = lane & 3;
    const long pbase = (long)e * N_NODES * D_DIM;
#pragma unroll
    for (int mt = 0; mt < 4; mt++) {
        int r0 = t0 + warpM * 64 + mt * 16 + gr;
#pragma unroll
        for (int nt = 0; nt < 4; nt++) {
            int col = warpN * 32 + nt * 8 + 2 * idx;
            store_split2(g_part_hi, g_part_lo, pbase + (long)r0 * D_DIM + col,
                         acc[mt][nt][0], acc[mt][nt][1]);
            store_split2(g_part_hi, g_part_lo, pbase + (long)(r0 + 8) * D_DIM + col,
                         acc[mt][nt][2], acc[mt][nt][3]);
        }
    }
}

/* ---------------- reduce 8 bf16-split partials + bias (2-wide, high-parallelism) -- */
__global__ void reduce_bias(const float* __restrict__ bias)
{
    long idx = ((long)blockIdx.x * 256 + threadIdx.x) * 2;   /* < 262144 */
    float sx = bias[idx & 127], sy = bias[(idx + 1) & 127];
#pragma unroll
    for (int p = 0; p < 8; p++) {
        __nv_bfloat162 h = *(const __nv_bfloat162*)&g_part_hi[(long)p * 262144 + idx];
        __nv_bfloat162 l = *(const __nv_bfloat162*)&g_part_lo[(long)p * 262144 + idx];
        sx += __bfloat162float(h.x) + __bfloat162float(l.x);
        sy += __bfloat162float(h.y) + __bfloat162float(l.y);
    }
    *(float2*)&g_scratch[OFF_MSG + idx] = make_float2(sx, sy);
}

/* ---------------- GRU elementwise update ---------------- */
__global__ void gru_kernel(int cur)
{
    int idx = blockIdx.x * 256 + threadIdx.x;
    int i = idx >> 7, d = idx & 127;
    const float* __restrict__ gi = g_scratch + OFF_GI;
    const float* __restrict__ gh = g_scratch + OFF_GH;
    const float* __restrict__ h  = g_scratch + (cur ? OFF_H1 : OFF_H0);
    float* __restrict__ ho = g_scratch + (cur ? OFF_H0 : OFF_H1);

    long base = (long)i * 384 + d;
    float ir = gi[base], iz = gi[base + 128], inn = gi[base + 256];
    float hr = gh[base], hz = gh[base + 128], hn  = gh[base + 256];
    float hv = h[idx];
    float r = 1.f / (1.f + expf(-(ir + hr)));
    float z = 1.f / (1.f + expf(-(iz + hz)));
    float n = tanhf(inn + r * hn);
    ho[idx] = (1.f - z) * n + z * hv;
}

/* ---------------- launcher: legal fork/join for edge_split overlap ---------------- */
extern "C" void kernel_launch(void* const* d_in, const int* in_sizes, int n_in,
                              void* d_out, int out_size)
{
    const float* node = (const float*)d_in[0];
    const float* edge = (const float*)d_in[1];
    const float* Wmsg = (const float*)d_in[2];
    const float* bmsg = (const float*)d_in[3];
    const float* Wi   = (const float*)d_in[4];
    const float* Wh   = (const float*)d_in[5];
    const float* bgru = (const float*)d_in[6];
    const float* Aro  = (const float*)d_in[7];
    float* out = (float*)d_out;

    float* scratch = nullptr;
    cudaGetSymbolAddress((void**)&scratch, g_scratch);
    float* H0  = scratch + OFF_H0;
    float* H1  = scratch + OFF_H1;
    float* MSG = scratch + OFF_MSG;
    float* GI  = scratch + OFF_GI;
    float* GH  = scratch + OFF_GH;
    float* HA  = scratch + OFF_HA;

    static cudaStream_t s1 = nullptr;
    static cudaEvent_t evF = nullptr, evE = nullptr;
    if (!s1) {
        cudaStreamCreateWithFlags(&s1, cudaStreamNonBlocking);
        cudaEventCreateWithFlags(&evF, cudaEventDisableTiming);
        cudaEventCreateWithFlags(&evE, cudaEventDisableTiming);
    }

    cudaFuncSetAttribute(msg_mma_kernel, cudaFuncAttributeMaxDynamicSharedMemorySize, 3 * STAGE_BYTES);
    cudaFuncSetAttribute(lin_mma, cudaFuncAttributeMaxDynamicSharedMemorySize, 131072);
    cudaFuncSetAttribute(lin2_mma, cudaFuncAttributeMaxDynamicSharedMemorySize, 131072);
    cudaFuncSetAttribute(pe_mma, cudaFuncAttributeMaxDynamicSharedMemorySize, 131072);
    cudaFuncSetAttribute(nt_mma, cudaFuncAttributeMaxDynamicSharedMemorySize, 131072);

    /* fork: evF recorded on the capture-origin stream, s1 waits on it —
     * this is the capture-legal pattern (side stream must be forked from
     * an event recorded inside the capture). */
    cudaMemcpyAsync(H0, node, (size_t)N_NODES * D_DIM * sizeof(float),
                    cudaMemcpyDeviceToDevice);
    cudaEventRecord(evF, 0);
    cudaStreamWaitEvent(s1, evF, 0);
    edge_split_kernel<<<dim3(32, 128), 256, 0, s1>>>(edge);
    cudaEventRecord(evE, s1);

    int cur = 0;
    for (int it = 0; it < GITERS; it++) {
        float* Hc = cur ? H1 : H0;
        pe_mma<<<dim3(16, 8), 256, 131072>>>(Hc, Wmsg);
        if (it == 0) cudaStreamWaitEvent(0, evE, 0);   /* join before first msg */
        msg_mma_kernel<<<dim3(16, 8), 256, 3 * STAGE_BYTES>>>();
        reduce_bias<<<512, 256>>>(bmsg);
        lin2_mma<<<dim3(16, 3, 2), 256, 131072>>>(MSG, Hc, Wi, Wh, bgru, GI, GH);
        gru_kernel<<<1024, 256>>>(cur);
        cur ^= 1;
    }
    float* Hf = cur ? H1 : H0;
    lin_mma<<<dim3(16, 1), 256, 131072>>>(Hf, Aro, nullptr, HA, 128);
    nt_mma<<<dim3(16, 16), 256, 131072>>>(HA, Hf, out);
}